// round 1
// baseline (speedup 1.0000x reference)
#include <cuda_runtime.h>
#include <cuda_bf16.h>
#include <cfloat>
#include <math.h>

// ---------------- problem constants ----------------
#define BB 4
#define SS 1024
#define DD 2048
#define HQ 16
#define HKV 8
#define HD 128
#define GRP 2
#define EE 8
#define TOPK 2
#define FE 1024
#define FS 8192
#define TT (BB*SS)          // 4096 tokens
#define EPS 1e-6f

// ---------------- scratch layout (floats) ----------------
#define SZ_TD   ((size_t)TT*DD)        // 8,388,608
#define SZ_TKV  ((size_t)TT*HKV*HD)    // 4,194,304
#define SZ_TFS  ((size_t)TT*FS)        // 33,554,432
#define SZ_TFE  ((size_t)TT*FE)        // 4,194,304

#define OFF_LNX   ((size_t)0)
#define OFF_Q     (OFF_LNX  + SZ_TD)
#define OFF_K     (OFF_Q    + SZ_TD)
#define OFF_V     (OFF_K    + SZ_TKV)
#define OFF_O     (OFF_V    + SZ_TKV)
#define OFF_ATTN  (OFF_O    + SZ_TD)
#define OFF_H     (OFF_ATTN + SZ_TD)
#define OFF_FFIN  (OFF_H    + SZ_TD)
#define OFF_G0    (OFF_FFIN + SZ_TD)
#define OFF_G1    (OFF_G0   + SZ_TFS)
#define OFF_SH    (OFF_G1   + SZ_TFS)
#define OFF_RIN   (OFF_SH   + SZ_TD)
#define OFF_GIN   (OFF_RIN  + SZ_TD)
#define OFF_ROUT  (OFF_GIN  + SZ_TD)
#define OFF_COMB  (OFF_ROUT + SZ_TD)
#define OFF_EG0   (OFF_COMB + (size_t)TT*EE)
#define OFF_EG1   (OFF_EG0  + SZ_TFE)
#define OFF_PSUM  (OFF_EG1  + SZ_TFE)
#define SCRATCH_TOTAL (OFF_PSUM + 8)

__device__ float g_scratch[SCRATCH_TOTAL];
__device__ int   g_iscratch[EE*TT + EE];   // idx lists then counts

// ---------------- helpers ----------------
__device__ __forceinline__ float gelu_tanh(float v) {
    const float c = 0.7978845608028654f;
    float u = c * (v + 0.044715f * v * v * v);
    return 0.5f * v * (1.0f + tanhf(u));
}

// ---------------- RMS norm over D=2048, generic epilogue ----------------
// out[row] = (x*inv*scale*cmul + res1 + res2) * (*scalarPtr)
__global__ void rms_kernel(const float* __restrict__ in,
                           const float* __restrict__ scale, float cmul,
                           const float* __restrict__ res1,
                           const float* __restrict__ res2,
                           const float* __restrict__ scalarPtr,
                           float* __restrict__ out)
{
    int row = blockIdx.x;
    int tid = threadIdx.x;
    const float* xr = in + (size_t)row * DD;
    float ss = 0.f;
    for (int d = tid; d < DD; d += 256) { float v = xr[d]; ss += v * v; }
    for (int o = 16; o > 0; o >>= 1) ss += __shfl_xor_sync(0xffffffffu, ss, o);
    __shared__ float wsum[8];
    if ((tid & 31) == 0) wsum[tid >> 5] = ss;
    __syncthreads();
    float tot = 0.f;
    #pragma unroll
    for (int w = 0; w < 8; w++) tot += wsum[w];
    float inv = rsqrtf(tot * (1.0f / DD) + EPS);
    float sc = scalarPtr ? *scalarPtr : 1.0f;
    for (int d = tid; d < DD; d += 256) {
        float y = xr[d] * inv;
        if (scale) y *= scale[d];
        y *= cmul;
        if (res1) y += res1[(size_t)row * DD + d];
        if (res2) y += res2[(size_t)row * DD + d];
        out[(size_t)row * DD + d] = y * sc;
    }
}

// ---------------- per-head RMS (+ optional RoPE), HD=128 ----------------
__global__ void head_norm_rope_kernel(float* __restrict__ data,
                                      const float* __restrict__ scale,
                                      const int* __restrict__ positions,
                                      int H, int doRope)
{
    int idx = blockIdx.x;                  // (b*S + s)*H + h
    int tid = threadIdx.x;                 // 128
    int s = (idx / H) % SS;
    int b = idx / (H * SS);
    float* xr = data + (size_t)idx * HD;
    float v = xr[tid];
    float ss = v * v;
    for (int o = 16; o > 0; o >>= 1) ss += __shfl_xor_sync(0xffffffffu, ss, o);
    __shared__ float wsum[4];
    if ((tid & 31) == 0) wsum[tid >> 5] = ss;
    __syncthreads();
    float tot = wsum[0] + wsum[1] + wsum[2] + wsum[3];
    float y = v * rsqrtf(tot * (1.0f / HD) + EPS) * scale[tid];
    if (doRope) {
        __shared__ float tmp[HD];
        tmp[tid] = y;
        __syncthreads();
        int pos = positions[b * SS + s];
        int j = tid & 63;
        float inv = powf(10000.0f, -(float)j / 64.0f);
        float ang = (float)pos * inv;
        float sn, cs;
        sincosf(ang, &sn, &cs);
        float x1 = tmp[j], x2 = tmp[64 + j];
        y = (tid < 64) ? (x1 * cs - x2 * sn) : (x2 * cs + x1 * sn);
    }
    xr[tid] = y;
}

// ---------------- flash attention, no score scaling, causal ----------------
// grid (S, HQ, B), 128 threads; one block = one query row
#define TK 32
__global__ void attn_kernel(const float* __restrict__ q,
                            const float* __restrict__ k,
                            const float* __restrict__ v,
                            float* __restrict__ o)
{
    int b = blockIdx.z, h = blockIdx.y, qi = blockIdx.x;
    int hkv = h / GRP;
    int tid = threadIdx.x;
    __shared__ float qs[HD];
    __shared__ float ks[TK][HD];
    __shared__ float vs[TK][HD];
    __shared__ float ps[TK];
    __shared__ float s_alpha, s_l;

    qs[tid] = q[(((size_t)(b * SS + qi)) * HQ + h) * HD + tid];
    float m = -FLT_MAX, l = 0.f;      // authoritative in warp 0 lanes
    float acc = 0.f;                  // per-thread output dim

    for (int j0 = 0; j0 <= qi; j0 += TK) {
        int nk = min(TK, qi - j0 + 1);
        __syncthreads();  // protect ks/vs/ps from previous-iter readers (also covers qs first iter)
        #pragma unroll 4
        for (int t = 0; t < TK; t++) {
            if (t < nk) {
                size_t base = (((size_t)(b * SS + j0 + t)) * HKV + hkv) * HD + tid;
                ks[t][tid] = k[base];
                vs[t][tid] = v[base];
            }
        }
        __syncthreads();
        // scores: 4 threads per key, 32 dims each
        {
            int j = tid >> 2, part = tid & 3;
            float s = 0.f;
            const float* kr = ks[j];
            int d0 = part * 32;
            #pragma unroll
            for (int d = 0; d < 32; d++) s += qs[d0 + d] * kr[d0 + d];
            s += __shfl_xor_sync(0xffffffffu, s, 1);
            s += __shfl_xor_sync(0xffffffffu, s, 2);
            if (part == 0) ps[j] = (j < nk) ? s : -FLT_MAX;
        }
        __syncthreads();
        if (tid < 32) {
            float sj = ps[tid];
            float tmax = sj;
            for (int off = 16; off > 0; off >>= 1)
                tmax = fmaxf(tmax, __shfl_xor_sync(0xffffffffu, tmax, off));
            float mnew = fmaxf(m, tmax);
            float alpha = expf(m - mnew);
            float p = expf(sj - mnew);
            float psum = p;
            for (int off = 16; off > 0; off >>= 1)
                psum += __shfl_xor_sync(0xffffffffu, psum, off);
            l = l * alpha + psum;
            m = mnew;
            ps[tid] = p;
            if (tid == 0) { s_alpha = alpha; s_l = l; }
        }
        __syncthreads();
        float alpha = s_alpha;
        acc *= alpha;
        for (int t = 0; t < nk; t++) acc += ps[t] * vs[t][tid];
    }
    __syncthreads();
    o[(((size_t)(b * SS + qi)) * HQ + h) * HD + tid] = acc / s_l;
}

// ---------------- generic tiled SGEMM, optional gather-A / scatter-C ----------
// C[M,N] = A[M,K] * B[K,N]; N % 64 == 0, K % 16 == 0.
// aIdx: row gather for A. cIdx+combine: scatter C row & weighted accumulate.
// mCnt: dynamic row count.
__global__ void sgemm_kernel(const float* __restrict__ A,
                             const float* __restrict__ B,
                             float* __restrict__ C,
                             int M, int N, int K,
                             const int* __restrict__ aIdx,
                             const int* __restrict__ cIdx,
                             const int* __restrict__ mCnt,
                             const float* __restrict__ combine, int expert)
{
    int Meff = M;
    if (mCnt) Meff = min(M, *mCnt);
    int bm = blockIdx.y * 64;
    int bn = blockIdx.x * 64;
    if (bm >= Meff) return;

    __shared__ float As[16][64];
    __shared__ float Bs[16][64];
    int tid = threadIdx.x;
    int tr = tid >> 4, tc = tid & 15;
    float acc[4][4] = {};

    for (int k0 = 0; k0 < K; k0 += 16) {
        #pragma unroll
        for (int e = 0; e < 4; e++) {
            int lin = tid + e * 256;
            int mm = lin >> 4, kk = lin & 15;
            int gr = bm + mm;
            float va = 0.f;
            if (gr < Meff) {
                int ar = aIdx ? aIdx[gr] : gr;
                va = A[(size_t)ar * K + k0 + kk];
            }
            As[kk][mm] = va;
            int kk2 = lin >> 6, n2 = lin & 63;
            Bs[kk2][n2] = B[(size_t)(k0 + kk2) * N + bn + n2];
        }
        __syncthreads();
        #pragma unroll
        for (int kk = 0; kk < 16; kk++) {
            float4 a4 = *reinterpret_cast<const float4*>(&As[kk][tr * 4]);
            float4 b4 = *reinterpret_cast<const float4*>(&Bs[kk][tc * 4]);
            float a0 = a4.x, a1 = a4.y, a2 = a4.z, a3 = a4.w;
            float b0 = b4.x, b1 = b4.y, b2 = b4.z, b3 = b4.w;
            acc[0][0] += a0*b0; acc[0][1] += a0*b1; acc[0][2] += a0*b2; acc[0][3] += a0*b3;
            acc[1][0] += a1*b0; acc[1][1] += a1*b1; acc[1][2] += a1*b2; acc[1][3] += a1*b3;
            acc[2][0] += a2*b0; acc[2][1] += a2*b1; acc[2][2] += a2*b2; acc[2][3] += a2*b3;
            acc[3][0] += a3*b0; acc[3][1] += a3*b1; acc[3][2] += a3*b2; acc[3][3] += a3*b3;
        }
        __syncthreads();
    }
    #pragma unroll
    for (int i = 0; i < 4; i++) {
        int row = bm + tr * 4 + i;
        if (row >= Meff) continue;
        int crow = cIdx ? cIdx[row] : row;
        float* cp = C + (size_t)crow * N + bn + tc * 4;
        if (combine) {
            float w = combine[crow * EE + expert];
            #pragma unroll
            for (int j = 0; j < 4; j++) cp[j] += w * acc[i][j];
        } else {
            #pragma unroll
            for (int j = 0; j < 4; j++) cp[j] = acc[i][j];
        }
    }
}

// ---------------- elementwise gated GELU: g0 = gelu(g0) * g1 ----------------
__global__ void gelumul_kernel(float* __restrict__ g0, const float* __restrict__ g1,
                               size_t n, const int* __restrict__ cntPtr, int perRow)
{
    size_t i = (size_t)blockIdx.x * blockDim.x + threadIdx.x;
    size_t lim = cntPtr ? (size_t)(*cntPtr) * (size_t)perRow : n;
    if (i < lim) {
        float a = g0[i];
        g0[i] = gelu_tanh(a) * g1[i];
    }
}

// ---------------- router: logits, softmax, top-2, lists, lb accumulators ----
__global__ void router_kernel(const float* __restrict__ gin,
                              const float* __restrict__ wg,
                              float* __restrict__ combine,
                              int* __restrict__ cnt,
                              int* __restrict__ idx,
                              float* __restrict__ psum)
{
    int tok = blockIdx.x;
    int tid = threadIdx.x;  // 256
    float s[EE] = {};
    const float* g = gin + (size_t)tok * DD;
    for (int d = tid; d < DD; d += 256) {
        float gv = g[d];
        const float* w = wg + d * EE;
        #pragma unroll
        for (int e = 0; e < EE; e++) s[e] += gv * w[e];
    }
    __shared__ float sh[256][EE];
    #pragma unroll
    for (int e = 0; e < EE; e++) sh[tid][e] = s[e];
    __syncthreads();
    for (int str = 128; str > 0; str >>= 1) {
        if (tid < str) {
            #pragma unroll
            for (int e = 0; e < EE; e++) sh[tid][e] += sh[tid + str][e];
        }
        __syncthreads();
    }
    if (tid == 0) {
        float lg[EE], pe[EE];
        float mx = -FLT_MAX;
        #pragma unroll
        for (int e = 0; e < EE; e++) { lg[e] = sh[0][e]; mx = fmaxf(mx, lg[e]); }
        float sum = 0.f;
        #pragma unroll
        for (int e = 0; e < EE; e++) { pe[e] = expf(lg[e] - mx); sum += pe[e]; }
        float inv = 1.0f / sum;
        #pragma unroll
        for (int e = 0; e < EE; e++) { pe[e] *= inv; atomicAdd(&psum[e], pe[e]); }
        int i0 = 0;
        #pragma unroll
        for (int e = 1; e < EE; e++) if (pe[e] > pe[i0]) i0 = e;
        int i1 = (i0 == 0) ? 1 : 0;
        #pragma unroll
        for (int e = 0; e < EE; e++) if (e != i0 && e != i1 && pe[e] > pe[i1]) i1 = e;
        float tot = pe[i0] + pe[i1];
        float w0 = pe[i0] / tot, w1 = pe[i1] / tot;
        float* crow = combine + (size_t)tok * EE;
        #pragma unroll
        for (int e = 0; e < EE; e++) crow[e] = 0.f;
        crow[i0] = w0; crow[i1] = w1;
        int p0 = atomicAdd(&cnt[i0], 1); idx[i0 * TT + p0] = tok;
        int p1 = atomicAdd(&cnt[i1], 1); idx[i1 * TT + p1] = tok;
    }
}

// ---------------- load-balance loss ----------------
__global__ void lb_kernel(const int* __restrict__ cnt, const float* __restrict__ psum,
                          float* __restrict__ out)
{
    float lb = 0.f;
    #pragma unroll
    for (int e = 0; e < EE; e++)
        lb += ((float)cnt[e] / (float)TT) * (psum[e] / (float)TT);
    out[0] = lb * ((float)(EE * EE) / (float)EE);  // mean over E then *E^2
}

// ==================== host launcher ====================
extern "C" void kernel_launch(void* const* d_in, const int* in_sizes, int n_in,
                              void* d_out, int out_size)
{
    const int*   positions       = (const int*)  d_in[0];
    const float* x               = (const float*)d_in[1];
    const float* pre_attn_scale  = (const float*)d_in[2];
    const float* wq              = (const float*)d_in[3];
    const float* wk              = (const float*)d_in[4];
    const float* wv              = (const float*)d_in[5];
    const float* wo              = (const float*)d_in[6];
    const float* q_norm_scale    = (const float*)d_in[7];
    const float* k_norm_scale    = (const float*)d_in[8];
    const float* v_norm_scale    = (const float*)d_in[9];
    const float* post_attn_scale = (const float*)d_in[10];
    const float* pre_ffw_scale   = (const float*)d_in[11];
    const float* shared_wi0      = (const float*)d_in[12];
    const float* shared_wi1      = (const float*)d_in[13];
    const float* shared_wo       = (const float*)d_in[14];
    const float* post_ff1_scale  = (const float*)d_in[15];
    const float* pre_ff2_scale   = (const float*)d_in[16];
    const float* router_scale    = (const float*)d_in[17];
    const float* w_gate          = (const float*)d_in[18];
    const float* ewi0            = (const float*)d_in[19];
    const float* ewi1            = (const float*)d_in[20];
    const float* ewo             = (const float*)d_in[21];
    const float* post_ff2_scale  = (const float*)d_in[22];
    const float* layer_scalar    = (const float*)d_in[23];
    float* out = (float*)d_out;

    float* sc = nullptr;
    int*   isc = nullptr;
    cudaGetSymbolAddress((void**)&sc, g_scratch);
    cudaGetSymbolAddress((void**)&isc, g_iscratch);

    float* lnx   = sc + OFF_LNX;
    float* qb    = sc + OFF_Q;
    float* kb    = sc + OFF_K;
    float* vb    = sc + OFF_V;
    float* ob    = sc + OFF_O;
    float* attnb = sc + OFF_ATTN;
    float* hb    = sc + OFF_H;
    float* ffin  = sc + OFF_FFIN;
    float* g0    = sc + OFF_G0;
    float* g1    = sc + OFF_G1;
    float* shb   = sc + OFF_SH;
    float* rin   = sc + OFF_RIN;
    float* gin   = sc + OFF_GIN;
    float* routb = sc + OFF_ROUT;
    float* comb  = sc + OFF_COMB;
    float* eg0   = sc + OFF_EG0;
    float* eg1   = sc + OFF_EG1;
    float* psum  = sc + OFF_PSUM;
    int* idx = isc;
    int* cnt = isc + EE * TT;

    auto gemm = [&](const float* A, const float* Bm, float* C, int M, int N, int K,
                    const int* aIdx, const int* cIdx, const int* mc,
                    const float* cw, int ex) {
        dim3 grid(N / 64, (M + 63) / 64);
        sgemm_kernel<<<grid, 256>>>(A, Bm, C, M, N, K, aIdx, cIdx, mc, cw, ex);
    };

    // 1) pre-attn norm
    rms_kernel<<<TT, 256>>>(x, pre_attn_scale, 1.f, nullptr, nullptr, nullptr, lnx);

    // 2) QKV projections
    gemm(lnx, wq, qb, TT, HQ * HD, DD, nullptr, nullptr, nullptr, nullptr, 0);
    gemm(lnx, wk, kb, TT, HKV * HD, DD, nullptr, nullptr, nullptr, nullptr, 0);
    gemm(lnx, wv, vb, TT, HKV * HD, DD, nullptr, nullptr, nullptr, nullptr, 0);

    // 3) per-head norms + rope
    head_norm_rope_kernel<<<TT * HQ, HD>>>(qb, q_norm_scale, positions, HQ, 1);
    head_norm_rope_kernel<<<TT * HKV, HD>>>(kb, k_norm_scale, positions, HKV, 1);
    head_norm_rope_kernel<<<TT * HKV, HD>>>(vb, v_norm_scale, positions, HKV, 0);

    // 4) attention
    {
        dim3 grid(SS, HQ, BB);
        attn_kernel<<<grid, HD>>>(qb, kb, vb, ob);
    }

    // 5) output projection + post-attn norm + residual
    gemm(ob, wo, attnb, TT, DD, HQ * HD, nullptr, nullptr, nullptr, nullptr, 0);
    rms_kernel<<<TT, 256>>>(attnb, post_attn_scale, 1.f, x, nullptr, nullptr, hb);

    // 6) shared FFN
    rms_kernel<<<TT, 256>>>(hb, pre_ffw_scale, 1.f, nullptr, nullptr, nullptr, ffin);
    gemm(ffin, shared_wi0, g0, TT, FS, DD, nullptr, nullptr, nullptr, nullptr, 0);
    gemm(ffin, shared_wi1, g1, TT, FS, DD, nullptr, nullptr, nullptr, nullptr, 0);
    gelumul_kernel<<<(unsigned)(SZ_TFS / 256), 256>>>(g0, g1, SZ_TFS, nullptr, 0);
    gemm(g0, shared_wo, shb, TT, DD, FS, nullptr, nullptr, nullptr, nullptr, 0);
    rms_kernel<<<TT, 256>>>(shb, post_ff1_scale, 1.f, nullptr, nullptr, nullptr, shb);

    // 7) router inputs
    rms_kernel<<<TT, 256>>>(hb, pre_ff2_scale, 1.f, nullptr, nullptr, nullptr, rin);
    rms_kernel<<<TT, 256>>>(hb, router_scale, 0.02209708691207961f /*D^-0.5*/,
                            nullptr, nullptr, nullptr, gin);

    // 8) router + MoE dispatch
    cudaMemsetAsync(cnt, 0, EE * sizeof(int));
    cudaMemsetAsync(psum, 0, EE * sizeof(float));
    cudaMemsetAsync(routb, 0, SZ_TD * sizeof(float));
    router_kernel<<<TT, 256>>>(gin, w_gate, comb, cnt, idx, psum);

    for (int e = 0; e < EE; e++) {
        const int* eidx = idx + e * TT;
        const int* ecnt = cnt + e;
        const float* bwi0 = ewi0 + (size_t)e * DD * FE;
        const float* bwi1 = ewi1 + (size_t)e * DD * FE;
        const float* bwo  = ewo  + (size_t)e * FE * DD;
        gemm(rin, bwi0, eg0, TT, FE, DD, eidx, nullptr, ecnt, nullptr, 0);
        gemm(rin, bwi1, eg1, TT, FE, DD, eidx, nullptr, ecnt, nullptr, 0);
        gelumul_kernel<<<(unsigned)(SZ_TFE / 256), 256>>>(eg0, eg1, SZ_TFE, ecnt, FE);
        gemm(eg0, bwo, routb, TT, DD, FE, nullptr, eidx, ecnt, comb, e);
    }

    // 9) final combine: out = (rms(routed)*post_ff2 + shared + h) * layer_scalar
    rms_kernel<<<TT, 256>>>(routb, post_ff2_scale, 1.f, shb, hb, layer_scalar, out);

    // 10) lb loss (if present in output)
    if (out_size > TT * DD) {
        lb_kernel<<<1, 1>>>(cnt, psum, out + (size_t)TT * DD);
    }
}

// round 3
// speedup vs baseline: 1.5846x; 1.5846x over previous
#include <cuda_runtime.h>
#include <cuda_bf16.h>
#include <cfloat>
#include <math.h>

// ---------------- problem constants ----------------
#define BB 4
#define SS 1024
#define DD 2048
#define HQ 16
#define HKV 8
#define HD 128
#define GRP 2
#define EE 8
#define TOPK 2
#define FE 1024
#define FS 8192
#define TT (BB*SS)          // 4096 tokens
#define EPS 1e-6f

// ---------------- scratch layout (floats) ----------------
#define SZ_TD   ((size_t)TT*DD)
#define SZ_TKV  ((size_t)TT*HKV*HD)
#define SZ_TFS  ((size_t)TT*FS)
#define SZ_TFE  ((size_t)TT*FE)

#define OFF_LNX   ((size_t)0)
#define OFF_Q     (OFF_LNX  + SZ_TD)
#define OFF_K     (OFF_Q    + SZ_TD)
#define OFF_V     (OFF_K    + SZ_TKV)
#define OFF_O     (OFF_V    + SZ_TKV)
#define OFF_ATTN  (OFF_O    + SZ_TD)
#define OFF_H     (OFF_ATTN + SZ_TD)
#define OFF_FFIN  (OFF_H    + SZ_TD)
#define OFF_G0    (OFF_FFIN + SZ_TD)
#define OFF_G1    (OFF_G0   + SZ_TFS)
#define OFF_SH    (OFF_G1   + SZ_TFS)
#define OFF_RIN   (OFF_SH   + SZ_TD)
#define OFF_GIN   (OFF_RIN  + SZ_TD)
#define OFF_ROUT  (OFF_GIN  + SZ_TD)
#define OFF_COMB  (OFF_ROUT + SZ_TD)
#define OFF_EG0   (OFF_COMB + (size_t)TT*EE)
#define OFF_EG1   (OFF_EG0  + SZ_TFE)
#define OFF_PSUM  (OFF_EG1  + SZ_TFE)
#define SCRATCH_TOTAL (OFF_PSUM + 8)

__device__ float g_scratch[SCRATCH_TOTAL];
__device__ int   g_iscratch[EE*TT + EE];

// ---------------- helpers ----------------
__device__ __forceinline__ float gelu_tanh(float v) {
    const float c = 0.7978845608028654f;
    float u = c * (v + 0.044715f * v * v * v);
    return 0.5f * v * (1.0f + tanhf(u));
}
__device__ __forceinline__ unsigned f2tf32(float f) {
    unsigned r;
    asm("cvt.rna.tf32.f32 %0, %1;" : "=r"(r) : "f"(f));
    return r;
}

// ---------------- RMS norm over D=2048, generic epilogue ----------------
__global__ void rms_kernel(const float* __restrict__ in,
                           const float* __restrict__ scale, float cmul,
                           const float* __restrict__ res1,
                           const float* __restrict__ res2,
                           const float* __restrict__ scalarPtr,
                           float* __restrict__ out)
{
    int row = blockIdx.x;
    int tid = threadIdx.x;
    const float* xr = in + (size_t)row * DD;
    float ss = 0.f;
    for (int d = tid; d < DD; d += 256) { float v = xr[d]; ss += v * v; }
    for (int o = 16; o > 0; o >>= 1) ss += __shfl_xor_sync(0xffffffffu, ss, o);
    __shared__ float wsum[8];
    if ((tid & 31) == 0) wsum[tid >> 5] = ss;
    __syncthreads();
    float tot = 0.f;
    #pragma unroll
    for (int w = 0; w < 8; w++) tot += wsum[w];
    float inv = rsqrtf(tot * (1.0f / DD) + EPS);
    float sc = scalarPtr ? *scalarPtr : 1.0f;
    for (int d = tid; d < DD; d += 256) {
        float y = xr[d] * inv;
        if (scale) y *= scale[d];
        y *= cmul;
        if (res1) y += res1[(size_t)row * DD + d];
        if (res2) y += res2[(size_t)row * DD + d];
        out[(size_t)row * DD + d] = y * sc;
    }
}

// ---------------- per-head RMS (+ optional RoPE), HD=128 ----------------
__global__ void head_norm_rope_kernel(float* __restrict__ data,
                                      const float* __restrict__ scale,
                                      const int* __restrict__ positions,
                                      int H, int doRope)
{
    int idx = blockIdx.x;
    int tid = threadIdx.x;
    int s = (idx / H) % SS;
    int b = idx / (H * SS);
    float* xr = data + (size_t)idx * HD;
    float v = xr[tid];
    float ss = v * v;
    for (int o = 16; o > 0; o >>= 1) ss += __shfl_xor_sync(0xffffffffu, ss, o);
    __shared__ float wsum[4];
    if ((tid & 31) == 0) wsum[tid >> 5] = ss;
    __syncthreads();
    float tot = wsum[0] + wsum[1] + wsum[2] + wsum[3];
    float y = v * rsqrtf(tot * (1.0f / HD) + EPS) * scale[tid];
    if (doRope) {
        __shared__ float tmp[HD];
        tmp[tid] = y;
        __syncthreads();
        int pos = positions[b * SS + s];
        int j = tid & 63;
        float inv = powf(10000.0f, -(float)j / 64.0f);
        float ang = (float)pos * inv;
        float sn, cs;
        sincosf(ang, &sn, &cs);
        float x1 = tmp[j], x2 = tmp[64 + j];
        y = (tid < 64) ? (x1 * cs - x2 * sn) : (x2 * cs + x1 * sn);
    }
    xr[tid] = y;
}

// ---------------- flash attention, no score scaling, causal ----------------
#define TK 32
__global__ void attn_kernel(const float* __restrict__ q,
                            const float* __restrict__ k,
                            const float* __restrict__ v,
                            float* __restrict__ o)
{
    int b = blockIdx.z, h = blockIdx.y, qi = blockIdx.x;
    int hkv = h / GRP;
    int tid = threadIdx.x;
    __shared__ float qs[HD];
    __shared__ float ks[TK][HD];
    __shared__ float vs[TK][HD];
    __shared__ float ps[TK];
    __shared__ float s_alpha, s_l;

    qs[tid] = q[(((size_t)(b * SS + qi)) * HQ + h) * HD + tid];
    float m = -FLT_MAX, l = 0.f;
    float acc = 0.f;

    for (int j0 = 0; j0 <= qi; j0 += TK) {
        int nk = min(TK, qi - j0 + 1);
        __syncthreads();
        #pragma unroll 4
        for (int t = 0; t < TK; t++) {
            if (t < nk) {
                size_t base = (((size_t)(b * SS + j0 + t)) * HKV + hkv) * HD + tid;
                ks[t][tid] = k[base];
                vs[t][tid] = v[base];
            }
        }
        __syncthreads();
        {
            int j = tid >> 2, part = tid & 3;
            float s = 0.f;
            const float* kr = ks[j];
            int d0 = part * 32;
            #pragma unroll
            for (int d = 0; d < 32; d++) s += qs[d0 + d] * kr[d0 + d];
            s += __shfl_xor_sync(0xffffffffu, s, 1);
            s += __shfl_xor_sync(0xffffffffu, s, 2);
            if (part == 0) ps[j] = (j < nk) ? s : -FLT_MAX;
        }
        __syncthreads();
        if (tid < 32) {
            float sj = ps[tid];
            float tmax = sj;
            for (int off = 16; off > 0; off >>= 1)
                tmax = fmaxf(tmax, __shfl_xor_sync(0xffffffffu, tmax, off));
            float mnew = fmaxf(m, tmax);
            float alpha = expf(m - mnew);
            float p = expf(sj - mnew);
            float psum = p;
            for (int off = 16; off > 0; off >>= 1)
                psum += __shfl_xor_sync(0xffffffffu, psum, off);
            l = l * alpha + psum;
            m = mnew;
            ps[tid] = p;
            if (tid == 0) { s_alpha = alpha; s_l = l; }
        }
        __syncthreads();
        float alpha = s_alpha;
        acc *= alpha;
        for (int t = 0; t < nk; t++) acc += ps[t] * vs[t][tid];
    }
    __syncthreads();
    o[(((size_t)(b * SS + qi)) * HQ + h) * HD + tid] = acc / s_l;
}

// ---------------- 3xTF32 tensor-core GEMM ----------------
// C[M,N] = A[M,K] * B[K,N] with error-compensated TF32:
//   x = hi + lo (both tf32);  acc += hiA*hiB + hiA*loB + loA*hiB
// Block tile 128x128x32, 256 threads, 8 warps (4xM, 2xN), warp tile 32x64.
#define ASTRIDE 36   // 32 + 4 pad
#define BSTRIDE 136  // 128 + 8 pad
#define A_PLANE (128 * ASTRIDE)
#define B_PLANE (32 * BSTRIDE)
#define GEMM_SMEM_BYTES ((2 * A_PLANE + 2 * B_PLANE) * 4)

__global__ void __launch_bounds__(256)
mma_gemm_kernel(const float* __restrict__ A,
                const float* __restrict__ B,
                float* __restrict__ C,
                int M, int N, int K,
                const int* __restrict__ aIdx,
                const int* __restrict__ cIdx,
                const int* __restrict__ mCnt,
                const float* __restrict__ combine, int expert)
{
    int Meff = M;
    if (mCnt) Meff = min(M, *mCnt);
    int bm = blockIdx.y * 128;
    int bn = blockIdx.x * 128;
    if (bm >= Meff) return;

    extern __shared__ unsigned smem[];
    unsigned* AsH = smem;
    unsigned* AsL = AsH + A_PLANE;
    unsigned* BsH = AsL + A_PLANE;
    unsigned* BsL = BsH + B_PLANE;

    int tid = threadIdx.x;
    int wid = tid >> 5;
    int lane = tid & 31;
    int gid = lane >> 2;
    int tgid = lane & 3;
    int wm = (wid & 3) * 32;
    int wn = (wid >> 2) * 64;

    int a_m = tid >> 3;
    int a_kq = tid & 7;
    int b_k = tid >> 5;
    int b_f4 = tid & 31;

    float acc[2][8][4];
    #pragma unroll
    for (int i = 0; i < 2; i++)
        #pragma unroll
        for (int j = 0; j < 8; j++)
            #pragma unroll
            for (int c = 0; c < 4; c++) acc[i][j][c] = 0.f;

    for (int k0 = 0; k0 < K; k0 += 32) {
        // ---- load A tile (128 x 32), split hi/lo ----
        #pragma unroll
        for (int p = 0; p < 4; p++) {
            int m = a_m + 32 * p;
            int gr = bm + m;
            float4 va = make_float4(0.f, 0.f, 0.f, 0.f);
            if (gr < Meff) {
                int ar = aIdx ? aIdx[gr] : gr;
                va = *reinterpret_cast<const float4*>(A + (size_t)ar * K + k0 + a_kq * 4);
            }
            int base = m * ASTRIDE + a_kq * 4;
            float vv[4] = {va.x, va.y, va.z, va.w};
            #pragma unroll
            for (int c = 0; c < 4; c++) {
                unsigned hi = f2tf32(vv[c]);
                AsH[base + c] = hi;
                AsL[base + c] = f2tf32(vv[c] - __uint_as_float(hi));
            }
        }
        // ---- load B tile (32 x 128), split hi/lo ----
        #pragma unroll
        for (int p = 0; p < 4; p++) {
            int kk = b_k + 8 * p;
            float4 vb = *reinterpret_cast<const float4*>(B + (size_t)(k0 + kk) * N + bn + b_f4 * 4);
            int base = kk * BSTRIDE + b_f4 * 4;
            float vv[4] = {vb.x, vb.y, vb.z, vb.w};
            #pragma unroll
            for (int c = 0; c < 4; c++) {
                unsigned hi = f2tf32(vv[c]);
                BsH[base + c] = hi;
                BsL[base + c] = f2tf32(vv[c] - __uint_as_float(hi));
            }
        }
        __syncthreads();

        #pragma unroll
        for (int ks = 0; ks < 4; ks++) {
            int kk = ks * 8;
            unsigned afH[2][4], afL[2][4];
            #pragma unroll
            for (int mf = 0; mf < 2; mf++) {
                int mrow = wm + mf * 16 + gid;
                int i0 = mrow * ASTRIDE + kk + tgid;
                int i1 = (mrow + 8) * ASTRIDE + kk + tgid;
                afH[mf][0] = AsH[i0];     afL[mf][0] = AsL[i0];
                afH[mf][1] = AsH[i1];     afL[mf][1] = AsL[i1];
                afH[mf][2] = AsH[i0 + 4]; afL[mf][2] = AsL[i0 + 4];
                afH[mf][3] = AsH[i1 + 4]; afL[mf][3] = AsL[i1 + 4];
            }
            unsigned bfH[8][2], bfL[8][2];
            #pragma unroll
            for (int nf = 0; nf < 8; nf++) {
                int ncol = wn + nf * 8 + gid;
                int i0 = (kk + tgid) * BSTRIDE + ncol;
                int i1 = (kk + tgid + 4) * BSTRIDE + ncol;
                bfH[nf][0] = BsH[i0]; bfL[nf][0] = BsL[i0];
                bfH[nf][1] = BsH[i1]; bfL[nf][1] = BsL[i1];
            }
            #pragma unroll
            for (int mf = 0; mf < 2; mf++)
                #pragma unroll
                for (int nf = 0; nf < 8; nf++) {
                    // hi*lo + lo*hi first (small terms), then hi*hi
                    asm volatile(
                        "mma.sync.aligned.m16n8k8.row.col.f32.tf32.tf32.f32 "
                        "{%0,%1,%2,%3}, {%4,%5,%6,%7}, {%8,%9}, {%0,%1,%2,%3};"
                        : "+f"(acc[mf][nf][0]), "+f"(acc[mf][nf][1]),
                          "+f"(acc[mf][nf][2]), "+f"(acc[mf][nf][3])
                        : "r"(afH[mf][0]), "r"(afH[mf][1]),
                          "r"(afH[mf][2]), "r"(afH[mf][3]),
                          "r"(bfL[nf][0]), "r"(bfL[nf][1]));
                    asm volatile(
                        "mma.sync.aligned.m16n8k8.row.col.f32.tf32.tf32.f32 "
                        "{%0,%1,%2,%3}, {%4,%5,%6,%7}, {%8,%9}, {%0,%1,%2,%3};"
                        : "+f"(acc[mf][nf][0]), "+f"(acc[mf][nf][1]),
                          "+f"(acc[mf][nf][2]), "+f"(acc[mf][nf][3])
                        : "r"(afL[mf][0]), "r"(afL[mf][1]),
                          "r"(afL[mf][2]), "r"(afL[mf][3]),
                          "r"(bfH[nf][0]), "r"(bfH[nf][1]));
                    asm volatile(
                        "mma.sync.aligned.m16n8k8.row.col.f32.tf32.tf32.f32 "
                        "{%0,%1,%2,%3}, {%4,%5,%6,%7}, {%8,%9}, {%0,%1,%2,%3};"
                        : "+f"(acc[mf][nf][0]), "+f"(acc[mf][nf][1]),
                          "+f"(acc[mf][nf][2]), "+f"(acc[mf][nf][3])
                        : "r"(afH[mf][0]), "r"(afH[mf][1]),
                          "r"(afH[mf][2]), "r"(afH[mf][3]),
                          "r"(bfH[nf][0]), "r"(bfH[nf][1]));
                }
        }
        __syncthreads();
    }

    // ---- epilogue ----
    #pragma unroll
    for (int mf = 0; mf < 2; mf++) {
        #pragma unroll
        for (int half = 0; half < 2; half++) {
            int row = bm + wm + mf * 16 + gid + half * 8;
            if (row >= Meff) continue;
            int crow = cIdx ? cIdx[row] : row;
            float w = 1.f;
            if (combine) w = combine[crow * EE + expert];
            #pragma unroll
            for (int nf = 0; nf < 8; nf++) {
                int col = bn + wn + nf * 8 + 2 * tgid;
                float v0 = acc[mf][nf][half * 2 + 0];
                float v1 = acc[mf][nf][half * 2 + 1];
                float* cp = C + (size_t)crow * N + col;
                if (combine) {
                    cp[0] += w * v0;
                    cp[1] += w * v1;
                } else {
                    cp[0] = v0;
                    cp[1] = v1;
                }
            }
        }
    }
}

// ---------------- elementwise gated GELU ----------------
__global__ void gelumul_kernel(float* __restrict__ g0, const float* __restrict__ g1,
                               size_t n, const int* __restrict__ cntPtr, int perRow)
{
    size_t i = (size_t)blockIdx.x * blockDim.x + threadIdx.x;
    size_t lim = cntPtr ? (size_t)(*cntPtr) * (size_t)perRow : n;
    if (i < lim) {
        float a = g0[i];
        g0[i] = gelu_tanh(a) * g1[i];
    }
}

// ---------------- router ----------------
__global__ void router_kernel(const float* __restrict__ gin,
                              const float* __restrict__ wg,
                              float* __restrict__ combine,
                              int* __restrict__ cnt,
                              int* __restrict__ idx,
                              float* __restrict__ psum)
{
    int tok = blockIdx.x;
    int tid = threadIdx.x;
    float s[EE] = {};
    const float* g = gin + (size_t)tok * DD;
    for (int d = tid; d < DD; d += 256) {
        float gv = g[d];
        const float* w = wg + d * EE;
        #pragma unroll
        for (int e = 0; e < EE; e++) s[e] += gv * w[e];
    }
    __shared__ float sh[256][EE];
    #pragma unroll
    for (int e = 0; e < EE; e++) sh[tid][e] = s[e];
    __syncthreads();
    for (int str = 128; str > 0; str >>= 1) {
        if (tid < str) {
            #pragma unroll
            for (int e = 0; e < EE; e++) sh[tid][e] += sh[tid + str][e];
        }
        __syncthreads();
    }
    if (tid == 0) {
        float lg[EE], pe[EE];
        float mx = -FLT_MAX;
        #pragma unroll
        for (int e = 0; e < EE; e++) { lg[e] = sh[0][e]; mx = fmaxf(mx, lg[e]); }
        float sum = 0.f;
        #pragma unroll
        for (int e = 0; e < EE; e++) { pe[e] = expf(lg[e] - mx); sum += pe[e]; }
        float inv = 1.0f / sum;
        #pragma unroll
        for (int e = 0; e < EE; e++) { pe[e] *= inv; atomicAdd(&psum[e], pe[e]); }
        int i0 = 0;
        #pragma unroll
        for (int e = 1; e < EE; e++) if (pe[e] > pe[i0]) i0 = e;
        int i1 = (i0 == 0) ? 1 : 0;
        #pragma unroll
        for (int e = 0; e < EE; e++) if (e != i0 && e != i1 && pe[e] > pe[i1]) i1 = e;
        float tot = pe[i0] + pe[i1];
        float w0 = pe[i0] / tot, w1 = pe[i1] / tot;
        float* crow = combine + (size_t)tok * EE;
        #pragma unroll
        for (int e = 0; e < EE; e++) crow[e] = 0.f;
        crow[i0] = w0; crow[i1] = w1;
        int p0 = atomicAdd(&cnt[i0], 1); idx[i0 * TT + p0] = tok;
        int p1 = atomicAdd(&cnt[i1], 1); idx[i1 * TT + p1] = tok;
    }
}

// ---------------- load-balance loss ----------------
__global__ void lb_kernel(const int* __restrict__ cnt, const float* __restrict__ psum,
                          float* __restrict__ out)
{
    float lb = 0.f;
    #pragma unroll
    for (int e = 0; e < EE; e++)
        lb += ((float)cnt[e] / (float)TT) * (psum[e] / (float)TT);
    out[0] = lb * ((float)(EE * EE) / (float)EE);
}

// ==================== host launcher ====================
extern "C" void kernel_launch(void* const* d_in, const int* in_sizes, int n_in,
                              void* d_out, int out_size)
{
    const int*   positions       = (const int*)  d_in[0];
    const float* x               = (const float*)d_in[1];
    const float* pre_attn_scale  = (const float*)d_in[2];
    const float* wq              = (const float*)d_in[3];
    const float* wk              = (const float*)d_in[4];
    const float* wv              = (const float*)d_in[5];
    const float* wo              = (const float*)d_in[6];
    const float* q_norm_scale    = (const float*)d_in[7];
    const float* k_norm_scale    = (const float*)d_in[8];
    const float* v_norm_scale    = (const float*)d_in[9];
    const float* post_attn_scale = (const float*)d_in[10];
    const float* pre_ffw_scale   = (const float*)d_in[11];
    const float* shared_wi0      = (const float*)d_in[12];
    const float* shared_wi1      = (const float*)d_in[13];
    const float* shared_wo       = (const float*)d_in[14];
    const float* post_ff1_scale  = (const float*)d_in[15];
    const float* pre_ff2_scale   = (const float*)d_in[16];
    const float* router_scale    = (const float*)d_in[17];
    const float* w_gate          = (const float*)d_in[18];
    const float* ewi0            = (const float*)d_in[19];
    const float* ewi1            = (const float*)d_in[20];
    const float* ewo             = (const float*)d_in[21];
    const float* post_ff2_scale  = (const float*)d_in[22];
    const float* layer_scalar    = (const float*)d_in[23];
    float* out = (float*)d_out;

    static int smemConfigured = 0;
    if (!smemConfigured) {
        cudaFuncSetAttribute(mma_gemm_kernel,
                             cudaFuncAttributeMaxDynamicSharedMemorySize,
                             GEMM_SMEM_BYTES);
        smemConfigured = 1;
    }

    float* sc = nullptr;
    int*   isc = nullptr;
    cudaGetSymbolAddress((void**)&sc, g_scratch);
    cudaGetSymbolAddress((void**)&isc, g_iscratch);

    float* lnx   = sc + OFF_LNX;
    float* qb    = sc + OFF_Q;
    float* kb    = sc + OFF_K;
    float* vb    = sc + OFF_V;
    float* ob    = sc + OFF_O;
    float* attnb = sc + OFF_ATTN;
    float* hb    = sc + OFF_H;
    float* ffin  = sc + OFF_FFIN;
    float* g0    = sc + OFF_G0;
    float* g1    = sc + OFF_G1;
    float* shb   = sc + OFF_SH;
    float* rin   = sc + OFF_RIN;
    float* gin   = sc + OFF_GIN;
    float* routb = sc + OFF_ROUT;
    float* comb  = sc + OFF_COMB;
    float* eg0   = sc + OFF_EG0;
    float* eg1   = sc + OFF_EG1;
    float* psum  = sc + OFF_PSUM;
    int* idx = isc;
    int* cnt = isc + EE * TT;

    auto gemm = [&](const float* A, const float* Bm, float* C, int M, int N, int K,
                    const int* aIdx, const int* cIdx, const int* mc,
                    const float* cw, int ex) {
        dim3 grid(N / 128, (M + 127) / 128);
        mma_gemm_kernel<<<grid, 256, GEMM_SMEM_BYTES>>>(A, Bm, C, M, N, K,
                                                        aIdx, cIdx, mc, cw, ex);
    };

    // 1) pre-attn norm
    rms_kernel<<<TT, 256>>>(x, pre_attn_scale, 1.f, nullptr, nullptr, nullptr, lnx);

    // 2) QKV projections
    gemm(lnx, wq, qb, TT, HQ * HD, DD, nullptr, nullptr, nullptr, nullptr, 0);
    gemm(lnx, wk, kb, TT, HKV * HD, DD, nullptr, nullptr, nullptr, nullptr, 0);
    gemm(lnx, wv, vb, TT, HKV * HD, DD, nullptr, nullptr, nullptr, nullptr, 0);

    // 3) per-head norms + rope
    head_norm_rope_kernel<<<TT * HQ, HD>>>(qb, q_norm_scale, positions, HQ, 1);
    head_norm_rope_kernel<<<TT * HKV, HD>>>(kb, k_norm_scale, positions, HKV, 1);
    head_norm_rope_kernel<<<TT * HKV, HD>>>(vb, v_norm_scale, positions, HKV, 0);

    // 4) attention
    {
        dim3 grid(SS, HQ, BB);
        attn_kernel<<<grid, HD>>>(qb, kb, vb, ob);
    }

    // 5) output projection + post-attn norm + residual
    gemm(ob, wo, attnb, TT, DD, HQ * HD, nullptr, nullptr, nullptr, nullptr, 0);
    rms_kernel<<<TT, 256>>>(attnb, post_attn_scale, 1.f, x, nullptr, nullptr, hb);

    // 6) shared FFN
    rms_kernel<<<TT, 256>>>(hb, pre_ffw_scale, 1.f, nullptr, nullptr, nullptr, ffin);
    gemm(ffin, shared_wi0, g0, TT, FS, DD, nullptr, nullptr, nullptr, nullptr, 0);
    gemm(ffin, shared_wi1, g1, TT, FS, DD, nullptr, nullptr, nullptr, nullptr, 0);
    gelumul_kernel<<<(unsigned)(SZ_TFS / 256), 256>>>(g0, g1, SZ_TFS, nullptr, 0);
    gemm(g0, shared_wo, shb, TT, DD, FS, nullptr, nullptr, nullptr, nullptr, 0);
    rms_kernel<<<TT, 256>>>(shb, post_ff1_scale, 1.f, nullptr, nullptr, nullptr, shb);

    // 7) router inputs
    rms_kernel<<<TT, 256>>>(hb, pre_ff2_scale, 1.f, nullptr, nullptr, nullptr, rin);
    rms_kernel<<<TT, 256>>>(hb, router_scale, 0.02209708691207961f /*D^-0.5*/,
                            nullptr, nullptr, nullptr, gin);

    // 8) router + MoE dispatch
    cudaMemsetAsync(cnt, 0, EE * sizeof(int));
    cudaMemsetAsync(psum, 0, EE * sizeof(float));
    cudaMemsetAsync(routb, 0, SZ_TD * sizeof(float));
    router_kernel<<<TT, 256>>>(gin, w_gate, comb, cnt, idx, psum);

    for (int e = 0; e < EE; e++) {
        const int* eidx = idx + e * TT;
        const int* ecnt = cnt + e;
        const float* bwi0 = ewi0 + (size_t)e * DD * FE;
        const float* bwi1 = ewi1 + (size_t)e * DD * FE;
        const float* bwo  = ewo  + (size_t)e * FE * DD;
        gemm(rin, bwi0, eg0, TT, FE, DD, eidx, nullptr, ecnt, nullptr, 0);
        gemm(rin, bwi1, eg1, TT, FE, DD, eidx, nullptr, ecnt, nullptr, 0);
        gelumul_kernel<<<(unsigned)(SZ_TFE / 256), 256>>>(eg0, eg1, SZ_TFE, ecnt, FE);
        gemm(eg0, bwo, routb, TT, DD, FE, nullptr, eidx, ecnt, comb, e);
    }

    // 9) final combine
    rms_kernel<<<TT, 256>>>(routb, post_ff2_scale, 1.f, shb, hb, layer_scalar, out);

    // 10) lb loss
    if (out_size > TT * DD) {
        lb_kernel<<<1, 1>>>(cnt, psum, out + (size_t)TT * DD);
    }
}

// round 4
// speedup vs baseline: 1.9766x; 1.2473x over previous
#include <cuda_runtime.h>
#include <cuda_bf16.h>
#include <cfloat>
#include <math.h>

// ---------------- problem constants ----------------
#define BB 4
#define SS 1024
#define DD 2048
#define HQ 16
#define HKV 8
#define HD 128
#define GRP 2
#define EE 8
#define TOPK 2
#define FE 1024
#define FS 8192
#define TT (BB*SS)          // 4096 tokens
#define EPS 1e-6f

// ---------------- scratch layout (floats) ----------------
#define SZ_TD   ((size_t)TT*DD)
#define SZ_TKV  ((size_t)TT*HKV*HD)
#define SZ_TFS  ((size_t)TT*FS)
#define SZ_TFE  ((size_t)TT*FE)

#define OFF_LNX   ((size_t)0)
#define OFF_Q     (OFF_LNX  + SZ_TD)
#define OFF_K     (OFF_Q    + SZ_TD)
#define OFF_V     (OFF_K    + SZ_TKV)
#define OFF_O     (OFF_V    + SZ_TKV)
#define OFF_ATTN  (OFF_O    + SZ_TD)
#define OFF_H     (OFF_ATTN + SZ_TD)
#define OFF_FFIN  (OFF_H    + SZ_TD)
#define OFF_G0    (OFF_FFIN + SZ_TD)
#define OFF_G1    (OFF_G0   + SZ_TFS)
#define OFF_SH    (OFF_G1   + SZ_TFS)
#define OFF_RIN   (OFF_SH   + SZ_TD)
#define OFF_GIN   (OFF_RIN  + SZ_TD)
#define OFF_ROUT  (OFF_GIN  + SZ_TD)
#define OFF_COMB  (OFF_ROUT + SZ_TD)
#define OFF_EG0   (OFF_COMB + (size_t)TT*EE)
#define OFF_EG1   (OFF_EG0  + SZ_TFE)
#define OFF_PSUM  (OFF_EG1  + SZ_TFE)
#define SCRATCH_TOTAL (OFF_PSUM + 8)

__device__ float g_scratch[SCRATCH_TOTAL];
__device__ int   g_iscratch[EE*TT + EE];

// ---------------- helpers ----------------
__device__ __forceinline__ float gelu_tanh(float v) {
    const float c = 0.7978845608028654f;
    float u = c * (v + 0.044715f * v * v * v);
    return 0.5f * v * (1.0f + tanhf(u));
}
__device__ __forceinline__ unsigned f2tf32(float f) {
    unsigned r;
    asm("cvt.rna.tf32.f32 %0, %1;" : "=r"(r) : "f"(f));
    return r;
}
__device__ __forceinline__ unsigned pack_bf16(float x, float y) {
    __nv_bfloat162 t = __floats2bfloat162_rn(x, y);  // x -> low half
    return *reinterpret_cast<unsigned*>(&t);
}
// split x = hi + lo (both representable in bf16); returns packed words via refs
__device__ __forceinline__ void split_pack(float x, float y,
                                           unsigned &hiW, unsigned &loW0,
                                           float &hx, float &hy) {
    __nv_bfloat16 bx = __float2bfloat16_rn(x);
    __nv_bfloat16 by = __float2bfloat16_rn(y);
    hx = __bfloat162float(bx);
    hy = __bfloat162float(by);
    __nv_bfloat162 h2; h2.x = bx; h2.y = by;
    hiW = *reinterpret_cast<unsigned*>(&h2);
    loW0 = pack_bf16(x - hx, y - hy);
}

// ---------------- RMS norm over D=2048, generic epilogue ----------------
__global__ void rms_kernel(const float* __restrict__ in,
                           const float* __restrict__ scale, float cmul,
                           const float* __restrict__ res1,
                           const float* __restrict__ res2,
                           const float* __restrict__ scalarPtr,
                           float* __restrict__ out)
{
    int row = blockIdx.x;
    int tid = threadIdx.x;
    const float* xr = in + (size_t)row * DD;
    float ss = 0.f;
    for (int d = tid; d < DD; d += 256) { float v = xr[d]; ss += v * v; }
    for (int o = 16; o > 0; o >>= 1) ss += __shfl_xor_sync(0xffffffffu, ss, o);
    __shared__ float wsum[8];
    if ((tid & 31) == 0) wsum[tid >> 5] = ss;
    __syncthreads();
    float tot = 0.f;
    #pragma unroll
    for (int w = 0; w < 8; w++) tot += wsum[w];
    float inv = rsqrtf(tot * (1.0f / DD) + EPS);
    float sc = scalarPtr ? *scalarPtr : 1.0f;
    for (int d = tid; d < DD; d += 256) {
        float y = xr[d] * inv;
        if (scale) y *= scale[d];
        y *= cmul;
        if (res1) y += res1[(size_t)row * DD + d];
        if (res2) y += res2[(size_t)row * DD + d];
        out[(size_t)row * DD + d] = y * sc;
    }
}

// ---------------- per-head RMS (+ optional RoPE), HD=128 ----------------
__global__ void head_norm_rope_kernel(float* __restrict__ data,
                                      const float* __restrict__ scale,
                                      const int* __restrict__ positions,
                                      int H, int doRope)
{
    int idx = blockIdx.x;
    int tid = threadIdx.x;
    int s = (idx / H) % SS;
    int b = idx / (H * SS);
    float* xr = data + (size_t)idx * HD;
    float v = xr[tid];
    float ss = v * v;
    for (int o = 16; o > 0; o >>= 1) ss += __shfl_xor_sync(0xffffffffu, ss, o);
    __shared__ float wsum[4];
    if ((tid & 31) == 0) wsum[tid >> 5] = ss;
    __syncthreads();
    float tot = wsum[0] + wsum[1] + wsum[2] + wsum[3];
    float y = v * rsqrtf(tot * (1.0f / HD) + EPS) * scale[tid];
    if (doRope) {
        __shared__ float tmp[HD];
        tmp[tid] = y;
        __syncthreads();
        int pos = positions[b * SS + s];
        int j = tid & 63;
        float inv = powf(10000.0f, -(float)j / 64.0f);
        float ang = (float)pos * inv;
        float sn, cs;
        sincosf(ang, &sn, &cs);
        float x1 = tmp[j], x2 = tmp[64 + j];
        y = (tid < 64) ? (x1 * cs - x2 * sn) : (x2 * cs + x1 * sn);
    }
    xr[tid] = y;
}

// ---------------- flash attention, no score scaling, causal ----------------
#define TK 32
__global__ void attn_kernel(const float* __restrict__ q,
                            const float* __restrict__ k,
                            const float* __restrict__ v,
                            float* __restrict__ o)
{
    int b = blockIdx.z, h = blockIdx.y, qi = blockIdx.x;
    int hkv = h / GRP;
    int tid = threadIdx.x;
    __shared__ float qs[HD];
    __shared__ float ks[TK][HD];
    __shared__ float vs[TK][HD];
    __shared__ float ps[TK];
    __shared__ float s_alpha, s_l;

    qs[tid] = q[(((size_t)(b * SS + qi)) * HQ + h) * HD + tid];
    float m = -FLT_MAX, l = 0.f;
    float acc = 0.f;

    for (int j0 = 0; j0 <= qi; j0 += TK) {
        int nk = min(TK, qi - j0 + 1);
        __syncthreads();
        #pragma unroll 4
        for (int t = 0; t < TK; t++) {
            if (t < nk) {
                size_t base = (((size_t)(b * SS + j0 + t)) * HKV + hkv) * HD + tid;
                ks[t][tid] = k[base];
                vs[t][tid] = v[base];
            }
        }
        __syncthreads();
        {
            int j = tid >> 2, part = tid & 3;
            float s = 0.f;
            const float* kr = ks[j];
            int d0 = part * 32;
            #pragma unroll
            for (int d = 0; d < 32; d++) s += qs[d0 + d] * kr[d0 + d];
            s += __shfl_xor_sync(0xffffffffu, s, 1);
            s += __shfl_xor_sync(0xffffffffu, s, 2);
            if (part == 0) ps[j] = (j < nk) ? s : -FLT_MAX;
        }
        __syncthreads();
        if (tid < 32) {
            float sj = ps[tid];
            float tmax = sj;
            for (int off = 16; off > 0; off >>= 1)
                tmax = fmaxf(tmax, __shfl_xor_sync(0xffffffffu, tmax, off));
            float mnew = fmaxf(m, tmax);
            float alpha = expf(m - mnew);
            float p = expf(sj - mnew);
            float psum = p;
            for (int off = 16; off > 0; off >>= 1)
                psum += __shfl_xor_sync(0xffffffffu, psum, off);
            l = l * alpha + psum;
            m = mnew;
            ps[tid] = p;
            if (tid == 0) { s_alpha = alpha; s_l = l; }
        }
        __syncthreads();
        float alpha = s_alpha;
        acc *= alpha;
        for (int t = 0; t < nk; t++) acc += ps[t] * vs[t][tid];
    }
    __syncthreads();
    o[(((size_t)(b * SS + qi)) * HQ + h) * HD + tid] = acc / s_l;
}

// ================= 3xTF32 GEMM (precision path: QKV only) =================
#define ASTRIDE 36
#define BSTRIDE 136
#define A_PLANE (128 * ASTRIDE)
#define B_PLANE (32 * BSTRIDE)
#define GEMM_SMEM_BYTES ((2 * A_PLANE + 2 * B_PLANE) * 4)

__global__ void __launch_bounds__(256)
mma_gemm_kernel(const float* __restrict__ A,
                const float* __restrict__ B,
                float* __restrict__ C,
                int M, int N, int K,
                const int* __restrict__ aIdx,
                const int* __restrict__ cIdx,
                const int* __restrict__ mCnt,
                const float* __restrict__ combine, int expert)
{
    int Meff = M;
    if (mCnt) Meff = min(M, *mCnt);
    int bm = blockIdx.y * 128;
    int bn = blockIdx.x * 128;
    if (bm >= Meff) return;

    extern __shared__ unsigned smem[];
    unsigned* AsH = smem;
    unsigned* AsL = AsH + A_PLANE;
    unsigned* BsH = AsL + A_PLANE;
    unsigned* BsL = BsH + B_PLANE;

    int tid = threadIdx.x;
    int wid = tid >> 5;
    int lane = tid & 31;
    int gid = lane >> 2;
    int tgid = lane & 3;
    int wm = (wid & 3) * 32;
    int wn = (wid >> 2) * 64;

    int a_m = tid >> 3;
    int a_kq = tid & 7;
    int b_k = tid >> 5;
    int b_f4 = tid & 31;

    float acc[2][8][4];
    #pragma unroll
    for (int i = 0; i < 2; i++)
        #pragma unroll
        for (int j = 0; j < 8; j++)
            #pragma unroll
            for (int c = 0; c < 4; c++) acc[i][j][c] = 0.f;

    for (int k0 = 0; k0 < K; k0 += 32) {
        #pragma unroll
        for (int p = 0; p < 4; p++) {
            int m = a_m + 32 * p;
            int gr = bm + m;
            float4 va = make_float4(0.f, 0.f, 0.f, 0.f);
            if (gr < Meff) {
                int ar = aIdx ? aIdx[gr] : gr;
                va = *reinterpret_cast<const float4*>(A + (size_t)ar * K + k0 + a_kq * 4);
            }
            int base = m * ASTRIDE + a_kq * 4;
            float vv[4] = {va.x, va.y, va.z, va.w};
            #pragma unroll
            for (int c = 0; c < 4; c++) {
                unsigned hi = f2tf32(vv[c]);
                AsH[base + c] = hi;
                AsL[base + c] = f2tf32(vv[c] - __uint_as_float(hi));
            }
        }
        #pragma unroll
        for (int p = 0; p < 4; p++) {
            int kk = b_k + 8 * p;
            float4 vb = *reinterpret_cast<const float4*>(B + (size_t)(k0 + kk) * N + bn + b_f4 * 4);
            int base = kk * BSTRIDE + b_f4 * 4;
            float vv[4] = {vb.x, vb.y, vb.z, vb.w};
            #pragma unroll
            for (int c = 0; c < 4; c++) {
                unsigned hi = f2tf32(vv[c]);
                BsH[base + c] = hi;
                BsL[base + c] = f2tf32(vv[c] - __uint_as_float(hi));
            }
        }
        __syncthreads();

        #pragma unroll
        for (int ks = 0; ks < 4; ks++) {
            int kk = ks * 8;
            unsigned afH[2][4], afL[2][4];
            #pragma unroll
            for (int mf = 0; mf < 2; mf++) {
                int mrow = wm + mf * 16 + gid;
                int i0 = mrow * ASTRIDE + kk + tgid;
                int i1 = (mrow + 8) * ASTRIDE + kk + tgid;
                afH[mf][0] = AsH[i0];     afL[mf][0] = AsL[i0];
                afH[mf][1] = AsH[i1];     afL[mf][1] = AsL[i1];
                afH[mf][2] = AsH[i0 + 4]; afL[mf][2] = AsL[i0 + 4];
                afH[mf][3] = AsH[i1 + 4]; afL[mf][3] = AsL[i1 + 4];
            }
            unsigned bfH[8][2], bfL[8][2];
            #pragma unroll
            for (int nf = 0; nf < 8; nf++) {
                int ncol = wn + nf * 8 + gid;
                int i0 = (kk + tgid) * BSTRIDE + ncol;
                int i1 = (kk + tgid + 4) * BSTRIDE + ncol;
                bfH[nf][0] = BsH[i0]; bfL[nf][0] = BsL[i0];
                bfH[nf][1] = BsH[i1]; bfL[nf][1] = BsL[i1];
            }
            #pragma unroll
            for (int mf = 0; mf < 2; mf++)
                #pragma unroll
                for (int nf = 0; nf < 8; nf++) {
                    asm volatile(
                        "mma.sync.aligned.m16n8k8.row.col.f32.tf32.tf32.f32 "
                        "{%0,%1,%2,%3}, {%4,%5,%6,%7}, {%8,%9}, {%0,%1,%2,%3};"
                        : "+f"(acc[mf][nf][0]), "+f"(acc[mf][nf][1]),
                          "+f"(acc[mf][nf][2]), "+f"(acc[mf][nf][3])
                        : "r"(afH[mf][0]), "r"(afH[mf][1]),
                          "r"(afH[mf][2]), "r"(afH[mf][3]),
                          "r"(bfL[nf][0]), "r"(bfL[nf][1]));
                    asm volatile(
                        "mma.sync.aligned.m16n8k8.row.col.f32.tf32.tf32.f32 "
                        "{%0,%1,%2,%3}, {%4,%5,%6,%7}, {%8,%9}, {%0,%1,%2,%3};"
                        : "+f"(acc[mf][nf][0]), "+f"(acc[mf][nf][1]),
                          "+f"(acc[mf][nf][2]), "+f"(acc[mf][nf][3])
                        : "r"(afL[mf][0]), "r"(afL[mf][1]),
                          "r"(afL[mf][2]), "r"(afL[mf][3]),
                          "r"(bfH[nf][0]), "r"(bfH[nf][1]));
                    asm volatile(
                        "mma.sync.aligned.m16n8k8.row.col.f32.tf32.tf32.f32 "
                        "{%0,%1,%2,%3}, {%4,%5,%6,%7}, {%8,%9}, {%0,%1,%2,%3};"
                        : "+f"(acc[mf][nf][0]), "+f"(acc[mf][nf][1]),
                          "+f"(acc[mf][nf][2]), "+f"(acc[mf][nf][3])
                        : "r"(afH[mf][0]), "r"(afH[mf][1]),
                          "r"(afH[mf][2]), "r"(afH[mf][3]),
                          "r"(bfH[nf][0]), "r"(bfH[nf][1]));
                }
        }
        __syncthreads();
    }

    #pragma unroll
    for (int mf = 0; mf < 2; mf++) {
        #pragma unroll
        for (int half = 0; half < 2; half++) {
            int row = bm + wm + mf * 16 + gid + half * 8;
            if (row >= Meff) continue;
            int crow = cIdx ? cIdx[row] : row;
            float w = 1.f;
            if (combine) w = combine[crow * EE + expert];
            #pragma unroll
            for (int nf = 0; nf < 8; nf++) {
                int col = bn + wn + nf * 8 + 2 * tgid;
                float v0 = acc[mf][nf][half * 2 + 0];
                float v1 = acc[mf][nf][half * 2 + 1];
                float* cp = C + (size_t)crow * N + col;
                if (combine) {
                    cp[0] += w * v0;
                    cp[1] += w * v1;
                } else {
                    cp[0] = v0;
                    cp[1] = v1;
                }
            }
        }
    }
}

// ================= bf16x2 GEMM (bulk path) =================
// C = A*B via hi/lo bf16 split: acc += Ah*Bh + Ah*Bl + Al*Bh.
// Block tile 128x128x32, 256 thr, warp tile 32x64, mma.m16n8k16.bf16.
// As planes: bf16 [m][k], row stride 20 words (40 bf16, 80B = 5 groups -> LDSM conflict-free)
// Bs planes: bf16 [k][n], row stride 68 words (136 bf16, 272B = 17 groups -> conflict-free)
#define BAST 20
#define BBST 68

__global__ void __launch_bounds__(256, 2)
bf16_gemm_kernel(const float* __restrict__ A,
                 const float* __restrict__ B,
                 float* __restrict__ C,
                 int M, int N, int K,
                 const int* __restrict__ aIdx,
                 const int* __restrict__ cIdx,
                 const int* __restrict__ mCnt,
                 const float* __restrict__ combine, int expert)
{
    int Meff = M;
    if (mCnt) Meff = min(M, *mCnt);
    int bm = blockIdx.y * 128;
    int bn = blockIdx.x * 128;
    if (bm >= Meff) return;

    __shared__ unsigned AsH[128 * BAST];
    __shared__ unsigned AsL[128 * BAST];
    __shared__ unsigned BsH[32 * BBST];
    __shared__ unsigned BsL[32 * BBST];

    int tid = threadIdx.x;
    int wid = tid >> 5;
    int lane = tid & 31;
    int gid = lane >> 2;
    int tgid = lane & 3;
    int wm = (wid & 3) * 32;
    int wn = (wid >> 2) * 64;

    int a_m = tid >> 3;
    int a_kq = tid & 7;   // float4 along k
    int b_k = tid >> 5;
    int b_f4 = tid & 31;  // float4 along n

    // ldmatrix lane addressing (byte offsets)
    unsigned aBaseH = (unsigned)__cvta_generic_to_shared(AsH);
    unsigned aBaseL = (unsigned)__cvta_generic_to_shared(AsL);
    unsigned bBaseH = (unsigned)__cvta_generic_to_shared(BsH);
    unsigned bBaseL = (unsigned)__cvta_generic_to_shared(BsL);
    int l15 = lane & 15;
    int lHi8 = (lane >> 4) << 3;   // 0 or 8

    float acc[2][8][4];
    #pragma unroll
    for (int i = 0; i < 2; i++)
        #pragma unroll
        for (int j = 0; j < 8; j++)
            #pragma unroll
            for (int c = 0; c < 4; c++) acc[i][j][c] = 0.f;

    for (int k0 = 0; k0 < K; k0 += 32) {
        // ---- fill A (128 x 32) hi/lo packed bf16 words ----
        #pragma unroll
        for (int p = 0; p < 4; p++) {
            int m = a_m + 32 * p;
            int gr = bm + m;
            float4 va = make_float4(0.f, 0.f, 0.f, 0.f);
            if (gr < Meff) {
                int ar = aIdx ? aIdx[gr] : gr;
                va = *reinterpret_cast<const float4*>(A + (size_t)ar * K + k0 + a_kq * 4);
            }
            int base = m * BAST + 2 * a_kq;
            unsigned h0, l0, h1, l1; float hx, hy;
            split_pack(va.x, va.y, h0, l0, hx, hy);
            split_pack(va.z, va.w, h1, l1, hx, hy);
            AsH[base] = h0; AsH[base + 1] = h1;
            AsL[base] = l0; AsL[base + 1] = l1;
        }
        // ---- fill B (32 x 128) hi/lo ----
        #pragma unroll
        for (int p = 0; p < 4; p++) {
            int kk = b_k + 8 * p;
            float4 vb = *reinterpret_cast<const float4*>(B + (size_t)(k0 + kk) * N + bn + b_f4 * 4);
            int base = kk * BBST + 2 * b_f4;
            unsigned h0, l0, h1, l1; float hx, hy;
            split_pack(vb.x, vb.y, h0, l0, hx, hy);
            split_pack(vb.z, vb.w, h1, l1, hx, hy);
            BsH[base] = h0; BsH[base + 1] = h1;
            BsL[base] = l0; BsL[base + 1] = l1;
        }
        __syncthreads();

        #pragma unroll
        for (int ks = 0; ks < 2; ks++) {
            int kk = ks * 16;
            // A fragments (hi & lo) via ldmatrix x4
            unsigned ah[2][4], al[2][4];
            #pragma unroll
            for (int mf = 0; mf < 2; mf++) {
                int mrow = wm + mf * 16 + l15;
                unsigned off = (unsigned)(mrow * (BAST * 4) + (kk + lHi8) * 2);
                asm volatile("ldmatrix.sync.aligned.m8n8.x4.shared.b16 {%0,%1,%2,%3}, [%4];"
                             : "=r"(ah[mf][0]), "=r"(ah[mf][1]), "=r"(ah[mf][2]), "=r"(ah[mf][3])
                             : "r"(aBaseH + off));
                asm volatile("ldmatrix.sync.aligned.m8n8.x4.shared.b16 {%0,%1,%2,%3}, [%4];"
                             : "=r"(al[mf][0]), "=r"(al[mf][1]), "=r"(al[mf][2]), "=r"(al[mf][3])
                             : "r"(aBaseL + off));
            }
            // B hi fragments via ldmatrix.trans, then Ah*Bh + Al*Bh
            unsigned bfr[8][2];
            {
                int krow = kk + l15;
                #pragma unroll
                for (int nfp = 0; nfp < 4; nfp++) {
                    int ncol = wn + nfp * 16 + lHi8;
                    unsigned off = (unsigned)(krow * (BBST * 4) + ncol * 2);
                    asm volatile("ldmatrix.sync.aligned.m8n8.x4.trans.shared.b16 {%0,%1,%2,%3}, [%4];"
                                 : "=r"(bfr[2 * nfp][0]), "=r"(bfr[2 * nfp][1]),
                                   "=r"(bfr[2 * nfp + 1][0]), "=r"(bfr[2 * nfp + 1][1])
                                 : "r"(bBaseH + off));
                }
            }
            #pragma unroll
            for (int mf = 0; mf < 2; mf++)
                #pragma unroll
                for (int nf = 0; nf < 8; nf++) {
                    asm volatile(
                        "mma.sync.aligned.m16n8k16.row.col.f32.bf16.bf16.f32 "
                        "{%0,%1,%2,%3}, {%4,%5,%6,%7}, {%8,%9}, {%0,%1,%2,%3};"
                        : "+f"(acc[mf][nf][0]), "+f"(acc[mf][nf][1]),
                          "+f"(acc[mf][nf][2]), "+f"(acc[mf][nf][3])
                        : "r"(ah[mf][0]), "r"(ah[mf][1]), "r"(ah[mf][2]), "r"(ah[mf][3]),
                          "r"(bfr[nf][0]), "r"(bfr[nf][1]));
                    asm volatile(
                        "mma.sync.aligned.m16n8k16.row.col.f32.bf16.bf16.f32 "
                        "{%0,%1,%2,%3}, {%4,%5,%6,%7}, {%8,%9}, {%0,%1,%2,%3};"
                        : "+f"(acc[mf][nf][0]), "+f"(acc[mf][nf][1]),
                          "+f"(acc[mf][nf][2]), "+f"(acc[mf][nf][3])
                        : "r"(al[mf][0]), "r"(al[mf][1]), "r"(al[mf][2]), "r"(al[mf][3]),
                          "r"(bfr[nf][0]), "r"(bfr[nf][1]));
                }
            // B lo fragments (reuse bfr), then Ah*Bl
            {
                int krow = kk + l15;
                #pragma unroll
                for (int nfp = 0; nfp < 4; nfp++) {
                    int ncol = wn + nfp * 16 + lHi8;
                    unsigned off = (unsigned)(krow * (BBST * 4) + ncol * 2);
                    asm volatile("ldmatrix.sync.aligned.m8n8.x4.trans.shared.b16 {%0,%1,%2,%3}, [%4];"
                                 : "=r"(bfr[2 * nfp][0]), "=r"(bfr[2 * nfp][1]),
                                   "=r"(bfr[2 * nfp + 1][0]), "=r"(bfr[2 * nfp + 1][1])
                                 : "r"(bBaseL + off));
                }
            }
            #pragma unroll
            for (int mf = 0; mf < 2; mf++)
                #pragma unroll
                for (int nf = 0; nf < 8; nf++) {
                    asm volatile(
                        "mma.sync.aligned.m16n8k16.row.col.f32.bf16.bf16.f32 "
                        "{%0,%1,%2,%3}, {%4,%5,%6,%7}, {%8,%9}, {%0,%1,%2,%3};"
                        : "+f"(acc[mf][nf][0]), "+f"(acc[mf][nf][1]),
                          "+f"(acc[mf][nf][2]), "+f"(acc[mf][nf][3])
                        : "r"(ah[mf][0]), "r"(ah[mf][1]), "r"(ah[mf][2]), "r"(ah[mf][3]),
                          "r"(bfr[nf][0]), "r"(bfr[nf][1]));
                }
        }
        __syncthreads();
    }

    // ---- epilogue (same layout as tf32 kernel) ----
    #pragma unroll
    for (int mf = 0; mf < 2; mf++) {
        #pragma unroll
        for (int half = 0; half < 2; half++) {
            int row = bm + wm + mf * 16 + gid + half * 8;
            if (row >= Meff) continue;
            int crow = cIdx ? cIdx[row] : row;
            float w = 1.f;
            if (combine) w = combine[crow * EE + expert];
            #pragma unroll
            for (int nf = 0; nf < 8; nf++) {
                int col = bn + wn + nf * 8 + 2 * tgid;
                float v0 = acc[mf][nf][half * 2 + 0];
                float v1 = acc[mf][nf][half * 2 + 1];
                float* cp = C + (size_t)crow * N + col;
                if (combine) {
                    cp[0] += w * v0;
                    cp[1] += w * v1;
                } else {
                    cp[0] = v0;
                    cp[1] = v1;
                }
            }
        }
    }
}

// ---------------- elementwise gated GELU ----------------
__global__ void gelumul_kernel(float* __restrict__ g0, const float* __restrict__ g1,
                               size_t n, const int* __restrict__ cntPtr, int perRow)
{
    size_t i = (size_t)blockIdx.x * blockDim.x + threadIdx.x;
    size_t lim = cntPtr ? (size_t)(*cntPtr) * (size_t)perRow : n;
    if (i < lim) {
        float a = g0[i];
        g0[i] = gelu_tanh(a) * g1[i];
    }
}

// ---------------- router ----------------
__global__ void router_kernel(const float* __restrict__ gin,
                              const float* __restrict__ wg,
                              float* __restrict__ combine,
                              int* __restrict__ cnt,
                              int* __restrict__ idx,
                              float* __restrict__ psum)
{
    int tok = blockIdx.x;
    int tid = threadIdx.x;
    float s[EE] = {};
    const float* g = gin + (size_t)tok * DD;
    for (int d = tid; d < DD; d += 256) {
        float gv = g[d];
        const float* w = wg + d * EE;
        #pragma unroll
        for (int e = 0; e < EE; e++) s[e] += gv * w[e];
    }
    __shared__ float sh[256][EE];
    #pragma unroll
    for (int e = 0; e < EE; e++) sh[tid][e] = s[e];
    __syncthreads();
    for (int str = 128; str > 0; str >>= 1) {
        if (tid < str) {
            #pragma unroll
            for (int e = 0; e < EE; e++) sh[tid][e] += sh[tid + str][e];
        }
        __syncthreads();
    }
    if (tid == 0) {
        float lg[EE], pe[EE];
        float mx = -FLT_MAX;
        #pragma unroll
        for (int e = 0; e < EE; e++) { lg[e] = sh[0][e]; mx = fmaxf(mx, lg[e]); }
        float sum = 0.f;
        #pragma unroll
        for (int e = 0; e < EE; e++) { pe[e] = expf(lg[e] - mx); sum += pe[e]; }
        float inv = 1.0f / sum;
        #pragma unroll
        for (int e = 0; e < EE; e++) { pe[e] *= inv; atomicAdd(&psum[e], pe[e]); }
        int i0 = 0;
        #pragma unroll
        for (int e = 1; e < EE; e++) if (pe[e] > pe[i0]) i0 = e;
        int i1 = (i0 == 0) ? 1 : 0;
        #pragma unroll
        for (int e = 0; e < EE; e++) if (e != i0 && e != i1 && pe[e] > pe[i1]) i1 = e;
        float tot = pe[i0] + pe[i1];
        float w0 = pe[i0] / tot, w1 = pe[i1] / tot;
        float* crow = combine + (size_t)tok * EE;
        #pragma unroll
        for (int e = 0; e < EE; e++) crow[e] = 0.f;
        crow[i0] = w0; crow[i1] = w1;
        int p0 = atomicAdd(&cnt[i0], 1); idx[i0 * TT + p0] = tok;
        int p1 = atomicAdd(&cnt[i1], 1); idx[i1 * TT + p1] = tok;
    }
}

// ---------------- load-balance loss ----------------
__global__ void lb_kernel(const int* __restrict__ cnt, const float* __restrict__ psum,
                          float* __restrict__ out)
{
    float lb = 0.f;
    #pragma unroll
    for (int e = 0; e < EE; e++)
        lb += ((float)cnt[e] / (float)TT) * (psum[e] / (float)TT);
    out[0] = lb * ((float)(EE * EE) / (float)EE);
}

// ==================== host launcher ====================
extern "C" void kernel_launch(void* const* d_in, const int* in_sizes, int n_in,
                              void* d_out, int out_size)
{
    const int*   positions       = (const int*)  d_in[0];
    const float* x               = (const float*)d_in[1];
    const float* pre_attn_scale  = (const float*)d_in[2];
    const float* wq              = (const float*)d_in[3];
    const float* wk              = (const float*)d_in[4];
    const float* wv              = (const float*)d_in[5];
    const float* wo              = (const float*)d_in[6];
    const float* q_norm_scale    = (const float*)d_in[7];
    const float* k_norm_scale    = (const float*)d_in[8];
    const float* v_norm_scale    = (const float*)d_in[9];
    const float* post_attn_scale = (const float*)d_in[10];
    const float* pre_ffw_scale   = (const float*)d_in[11];
    const float* shared_wi0      = (const float*)d_in[12];
    const float* shared_wi1      = (const float*)d_in[13];
    const float* shared_wo       = (const float*)d_in[14];
    const float* post_ff1_scale  = (const float*)d_in[15];
    const float* pre_ff2_scale   = (const float*)d_in[16];
    const float* router_scale    = (const float*)d_in[17];
    const float* w_gate          = (const float*)d_in[18];
    const float* ewi0            = (const float*)d_in[19];
    const float* ewi1            = (const float*)d_in[20];
    const float* ewo             = (const float*)d_in[21];
    const float* post_ff2_scale  = (const float*)d_in[22];
    const float* layer_scalar    = (const float*)d_in[23];
    float* out = (float*)d_out;

    static int smemConfigured = 0;
    if (!smemConfigured) {
        cudaFuncSetAttribute(mma_gemm_kernel,
                             cudaFuncAttributeMaxDynamicSharedMemorySize,
                             GEMM_SMEM_BYTES);
        smemConfigured = 1;
    }

    float* sc = nullptr;
    int*   isc = nullptr;
    cudaGetSymbolAddress((void**)&sc, g_scratch);
    cudaGetSymbolAddress((void**)&isc, g_iscratch);

    float* lnx   = sc + OFF_LNX;
    float* qb    = sc + OFF_Q;
    float* kb    = sc + OFF_K;
    float* vb    = sc + OFF_V;
    float* ob    = sc + OFF_O;
    float* attnb = sc + OFF_ATTN;
    float* hb    = sc + OFF_H;
    float* ffin  = sc + OFF_FFIN;
    float* g0    = sc + OFF_G0;
    float* g1    = sc + OFF_G1;
    float* shb   = sc + OFF_SH;
    float* rin   = sc + OFF_RIN;
    float* gin   = sc + OFF_GIN;
    float* routb = sc + OFF_ROUT;
    float* comb  = sc + OFF_COMB;
    float* eg0   = sc + OFF_EG0;
    float* eg1   = sc + OFF_EG1;
    float* psum  = sc + OFF_PSUM;
    int* idx = isc;
    int* cnt = isc + EE * TT;

    // precision path (QKV only)
    auto gemm_hi = [&](const float* A, const float* Bm, float* C, int M, int N, int K) {
        dim3 grid(N / 128, (M + 127) / 128);
        mma_gemm_kernel<<<grid, 256, GEMM_SMEM_BYTES>>>(A, Bm, C, M, N, K,
                                                        nullptr, nullptr, nullptr, nullptr, 0);
    };
    // bulk path
    auto gemm_bf = [&](const float* A, const float* Bm, float* C, int M, int N, int K,
                       const int* aIdx, const int* cIdx, const int* mc,
                       const float* cw, int ex) {
        dim3 grid(N / 128, (M + 127) / 128);
        bf16_gemm_kernel<<<grid, 256>>>(A, Bm, C, M, N, K, aIdx, cIdx, mc, cw, ex);
    };

    // 1) pre-attn norm
    rms_kernel<<<TT, 256>>>(x, pre_attn_scale, 1.f, nullptr, nullptr, nullptr, lnx);

    // 2) QKV projections (high precision: feeds unscaled QK^T)
    gemm_hi(lnx, wq, qb, TT, HQ * HD, DD);
    gemm_hi(lnx, wk, kb, TT, HKV * HD, DD);
    gemm_hi(lnx, wv, vb, TT, HKV * HD, DD);

    // 3) per-head norms + rope
    head_norm_rope_kernel<<<TT * HQ, HD>>>(qb, q_norm_scale, positions, HQ, 1);
    head_norm_rope_kernel<<<TT * HKV, HD>>>(kb, k_norm_scale, positions, HKV, 1);
    head_norm_rope_kernel<<<TT * HKV, HD>>>(vb, v_norm_scale, positions, HKV, 0);

    // 4) attention
    {
        dim3 grid(SS, HQ, BB);
        attn_kernel<<<grid, HD>>>(qb, kb, vb, ob);
    }

    // 5) output projection + post-attn norm + residual
    gemm_bf(ob, wo, attnb, TT, DD, HQ * HD, nullptr, nullptr, nullptr, nullptr, 0);
    rms_kernel<<<TT, 256>>>(attnb, post_attn_scale, 1.f, x, nullptr, nullptr, hb);

    // 6) shared FFN
    rms_kernel<<<TT, 256>>>(hb, pre_ffw_scale, 1.f, nullptr, nullptr, nullptr, ffin);
    gemm_bf(ffin, shared_wi0, g0, TT, FS, DD, nullptr, nullptr, nullptr, nullptr, 0);
    gemm_bf(ffin, shared_wi1, g1, TT, FS, DD, nullptr, nullptr, nullptr, nullptr, 0);
    gelumul_kernel<<<(unsigned)(SZ_TFS / 256), 256>>>(g0, g1, SZ_TFS, nullptr, 0);
    gemm_bf(g0, shared_wo, shb, TT, DD, FS, nullptr, nullptr, nullptr, nullptr, 0);
    rms_kernel<<<TT, 256>>>(shb, post_ff1_scale, 1.f, nullptr, nullptr, nullptr, shb);

    // 7) router inputs
    rms_kernel<<<TT, 256>>>(hb, pre_ff2_scale, 1.f, nullptr, nullptr, nullptr, rin);
    rms_kernel<<<TT, 256>>>(hb, router_scale, 0.02209708691207961f /*D^-0.5*/,
                            nullptr, nullptr, nullptr, gin);

    // 8) router + MoE dispatch
    cudaMemsetAsync(cnt, 0, EE * sizeof(int));
    cudaMemsetAsync(psum, 0, EE * sizeof(float));
    cudaMemsetAsync(routb, 0, SZ_TD * sizeof(float));
    router_kernel<<<TT, 256>>>(gin, w_gate, comb, cnt, idx, psum);

    for (int e = 0; e < EE; e++) {
        const int* eidx = idx + e * TT;
        const int* ecnt = cnt + e;
        const float* bwi0 = ewi0 + (size_t)e * DD * FE;
        const float* bwi1 = ewi1 + (size_t)e * DD * FE;
        const float* bwo  = ewo  + (size_t)e * FE * DD;
        gemm_bf(rin, bwi0, eg0, TT, FE, DD, eidx, nullptr, ecnt, nullptr, 0);
        gemm_bf(rin, bwi1, eg1, TT, FE, DD, eidx, nullptr, ecnt, nullptr, 0);
        gelumul_kernel<<<(unsigned)(SZ_TFE / 256), 256>>>(eg0, eg1, SZ_TFE, ecnt, FE);
        gemm_bf(eg0, bwo, routb, TT, DD, FE, nullptr, eidx, ecnt, comb, e);
    }

    // 9) final combine
    rms_kernel<<<TT, 256>>>(routb, post_ff2_scale, 1.f, shb, hb, layer_scalar, out);

    // 10) lb loss
    if (out_size > TT * DD) {
        lb_kernel<<<1, 1>>>(cnt, psum, out + (size_t)TT * DD);
    }
}

// round 5
// speedup vs baseline: 3.9526x; 1.9997x over previous
#include <cuda_runtime.h>
#include <cuda_bf16.h>
#include <cfloat>
#include <math.h>

// ---------------- problem constants ----------------
#define BB 4
#define SS 1024
#define DD 2048
#define HQ 16
#define HKV 8
#define HD 128
#define GRP 2
#define EE 8
#define TOPK 2
#define FE 1024
#define FS 8192
#define TT (BB*SS)          // 4096 tokens
#define EPS 1e-6f

// ---------------- scratch layout (floats) ----------------
#define SZ_TD   ((size_t)TT*DD)
#define SZ_TKV  ((size_t)TT*HKV*HD)
#define SZ_TFS  ((size_t)TT*FS)
#define SZ_TFE  ((size_t)TT*FE)

#define OFF_LNX   ((size_t)0)
#define OFF_Q     (OFF_LNX  + SZ_TD)
#define OFF_K     (OFF_Q    + SZ_TD)
#define OFF_V     (OFF_K    + SZ_TKV)
#define OFF_O     (OFF_V    + SZ_TKV)
#define OFF_ATTN  (OFF_O    + SZ_TD)
#define OFF_H     (OFF_ATTN + SZ_TD)
#define OFF_FFIN  (OFF_H    + SZ_TD)
#define OFF_G0    (OFF_FFIN + SZ_TD)
#define OFF_G1    (OFF_G0   + SZ_TFS)
#define OFF_SH    (OFF_G1   + SZ_TFS)
#define OFF_RIN   (OFF_SH   + SZ_TD)
#define OFF_GIN   (OFF_RIN  + SZ_TD)
#define OFF_ROUT  (OFF_GIN  + SZ_TD)
#define OFF_COMB  (OFF_ROUT + SZ_TD)
#define OFF_EG0   (OFF_COMB + (size_t)TT*EE)
#define OFF_EG1   (OFF_EG0  + SZ_TFE)
#define OFF_PSUM  (OFF_EG1  + SZ_TFE)
#define SCRATCH_TOTAL (OFF_PSUM + 8)

__device__ float g_scratch[SCRATCH_TOTAL];
__device__ int   g_iscratch[EE*TT + EE];

// ---------------- helpers ----------------
__device__ __forceinline__ float gelu_tanh(float v) {
    const float c = 0.7978845608028654f;
    float u = c * (v + 0.044715f * v * v * v);
    return 0.5f * v * (1.0f + tanhf(u));
}
__device__ __forceinline__ unsigned f2tf32(float f) {
    unsigned r;
    asm("cvt.rna.tf32.f32 %0, %1;" : "=r"(r) : "f"(f));
    return r;
}
__device__ __forceinline__ unsigned pack_bf16(float x, float y) {
    __nv_bfloat162 t = __floats2bfloat162_rn(x, y);  // x -> low half
    return *reinterpret_cast<unsigned*>(&t);
}
__device__ __forceinline__ void split_pack(float x, float y,
                                           unsigned &hiW, unsigned &loW0) {
    __nv_bfloat16 bx = __float2bfloat16_rn(x);
    __nv_bfloat16 by = __float2bfloat16_rn(y);
    float hx = __bfloat162float(bx);
    float hy = __bfloat162float(by);
    __nv_bfloat162 h2; h2.x = bx; h2.y = by;
    hiW = *reinterpret_cast<unsigned*>(&h2);
    loW0 = pack_bf16(x - hx, y - hy);
}

#define LDSM4(r0,r1,r2,r3,addr) \
    asm volatile("ldmatrix.sync.aligned.m8n8.x4.shared.b16 {%0,%1,%2,%3}, [%4];" \
                 : "=r"(r0),"=r"(r1),"=r"(r2),"=r"(r3) : "r"(addr))
#define LDSM4T(r0,r1,r2,r3,addr) \
    asm volatile("ldmatrix.sync.aligned.m8n8.x4.trans.shared.b16 {%0,%1,%2,%3}, [%4];" \
                 : "=r"(r0),"=r"(r1),"=r"(r2),"=r"(r3) : "r"(addr))
#define MMA_BF16(d0,d1,d2,d3,a0,a1,a2,a3,b0,b1) \
    asm volatile("mma.sync.aligned.m16n8k16.row.col.f32.bf16.bf16.f32 " \
                 "{%0,%1,%2,%3}, {%4,%5,%6,%7}, {%8,%9}, {%0,%1,%2,%3};" \
                 : "+f"(d0),"+f"(d1),"+f"(d2),"+f"(d3) \
                 : "r"(a0),"r"(a1),"r"(a2),"r"(a3),"r"(b0),"r"(b1))

// ---------------- RMS norm over D=2048, generic epilogue ----------------
__global__ void rms_kernel(const float* __restrict__ in,
                           const float* __restrict__ scale, float cmul,
                           const float* __restrict__ res1,
                           const float* __restrict__ res2,
                           const float* __restrict__ scalarPtr,
                           float* __restrict__ out)
{
    int row = blockIdx.x;
    int tid = threadIdx.x;
    const float* xr = in + (size_t)row * DD;
    float ss = 0.f;
    for (int d = tid; d < DD; d += 256) { float v = xr[d]; ss += v * v; }
    for (int o = 16; o > 0; o >>= 1) ss += __shfl_xor_sync(0xffffffffu, ss, o);
    __shared__ float wsum[8];
    if ((tid & 31) == 0) wsum[tid >> 5] = ss;
    __syncthreads();
    float tot = 0.f;
    #pragma unroll
    for (int w = 0; w < 8; w++) tot += wsum[w];
    float inv = rsqrtf(tot * (1.0f / DD) + EPS);
    float sc = scalarPtr ? *scalarPtr : 1.0f;
    for (int d = tid; d < DD; d += 256) {
        float y = xr[d] * inv;
        if (scale) y *= scale[d];
        y *= cmul;
        if (res1) y += res1[(size_t)row * DD + d];
        if (res2) y += res2[(size_t)row * DD + d];
        out[(size_t)row * DD + d] = y * sc;
    }
}

// ---------------- per-head RMS (+ optional RoPE), HD=128 ----------------
__global__ void head_norm_rope_kernel(float* __restrict__ data,
                                      const float* __restrict__ scale,
                                      const int* __restrict__ positions,
                                      int H, int doRope)
{
    int idx = blockIdx.x;
    int tid = threadIdx.x;
    int s = (idx / H) % SS;
    int b = idx / (H * SS);
    float* xr = data + (size_t)idx * HD;
    float v = xr[tid];
    float ss = v * v;
    for (int o = 16; o > 0; o >>= 1) ss += __shfl_xor_sync(0xffffffffu, ss, o);
    __shared__ float wsum[4];
    if ((tid & 31) == 0) wsum[tid >> 5] = ss;
    __syncthreads();
    float tot = wsum[0] + wsum[1] + wsum[2] + wsum[3];
    float y = v * rsqrtf(tot * (1.0f / HD) + EPS) * scale[tid];
    if (doRope) {
        __shared__ float tmp[HD];
        tmp[tid] = y;
        __syncthreads();
        int pos = positions[b * SS + s];
        int j = tid & 63;
        float inv = powf(10000.0f, -(float)j / 64.0f);
        float ang = (float)pos * inv;
        float sn, cs;
        sincosf(ang, &sn, &cs);
        float x1 = tmp[j], x2 = tmp[64 + j];
        y = (tid < 64) ? (x1 * cs - x2 * sn) : (x2 * cs + x1 * sn);
    }
    xr[tid] = y;
}

// ---------------- tensor-core flash attention ----------------
// Block: 128 q-rows x 1 head. 8 warps, each owns 16 rows (warp-local softmax).
// Key tiles of 64. bf16 hi/lo 3-MMA compensation for QK and PV.
#define ATQ 128
#define AKT 64
#define AST 68   // words per 128-dim row (272B = 17 16B-groups, odd -> LDSM conflict-free)
#define Q_WORDS (ATQ*AST)
#define KV_WORDS (AKT*AST)
#define ATT_SMEM_BYTES ((2*Q_WORDS + 4*KV_WORDS)*4)

__global__ void __launch_bounds__(256, 1)
fattn_kernel(const float* __restrict__ q,
             const float* __restrict__ k,
             const float* __restrict__ v,
             float* __restrict__ o)
{
    extern __shared__ unsigned att_smem[];
    unsigned* Qh = att_smem;
    unsigned* Ql = Qh + Q_WORDS;
    unsigned* Kh = Ql + Q_WORDS;
    unsigned* Kl = Kh + KV_WORDS;
    unsigned* Vh = Kl + KV_WORDS;
    unsigned* Vl = Vh + KV_WORDS;

    int b = blockIdx.z, h = blockIdx.y;
    int q0 = blockIdx.x * ATQ;
    int hkv = h / GRP;
    int tid = threadIdx.x, wid = tid >> 5, lane = tid & 31;
    int gid = lane >> 2, tgid = lane & 3;
    int l15 = lane & 15, lHi8 = (lane >> 4) << 3;

    unsigned qBaseH = (unsigned)__cvta_generic_to_shared(Qh);
    unsigned qBaseL = (unsigned)__cvta_generic_to_shared(Ql);
    unsigned kBaseH = (unsigned)__cvta_generic_to_shared(Kh);
    unsigned kBaseL = (unsigned)__cvta_generic_to_shared(Kl);
    unsigned vBaseH = (unsigned)__cvta_generic_to_shared(Vh);
    unsigned vBaseL = (unsigned)__cvta_generic_to_shared(Vl);

    // ---- fill Q (128 x 128) ----
    for (int i = tid; i < ATQ * 32; i += 256) {
        int row = i >> 5, c4 = i & 31;
        float4 vq = *(const float4*)(q + (((size_t)(b * SS + q0 + row)) * HQ + h) * HD + 4 * c4);
        unsigned h0, l0, h1, l1;
        split_pack(vq.x, vq.y, h0, l0);
        split_pack(vq.z, vq.w, h1, l1);
        int base = row * AST + c4 * 2;
        Qh[base] = h0; Qh[base + 1] = h1;
        Ql[base] = l0; Ql[base + 1] = l1;
    }

    float oacc[16][4];
    #pragma unroll
    for (int i = 0; i < 16; i++)
        #pragma unroll
        for (int c = 0; c < 4; c++) oacc[i][c] = 0.f;
    float m0 = -1e30f, m1 = -1e30f, l0r = 0.f, l1r = 0.f;

    int rowbase = q0 + wid * 16;
    // K-fragment lane addressing (B operand, non-trans x4):
    int kKey = (lane & 7) + ((lane >> 4) << 3);
    int kDimOff = (lane & 8) ? 8 : 0;

    int ntiles = (q0 >> 6) + 2;
    for (int jt = 0; jt < ntiles; jt++) {
        int j0 = jt * AKT;
        __syncthreads();
        // ---- fill K/V tile (64 x 128) ----
        for (int i = tid; i < AKT * 32; i += 256) {
            int row = i >> 5, c4 = i & 31;
            size_t gbase = (((size_t)(b * SS + j0 + row)) * HKV + hkv) * HD + 4 * c4;
            float4 vk = *(const float4*)(k + gbase);
            float4 vv = *(const float4*)(v + gbase);
            int base = row * AST + c4 * 2;
            unsigned h0, lo0, h1, lo1;
            split_pack(vk.x, vk.y, h0, lo0);
            split_pack(vk.z, vk.w, h1, lo1);
            Kh[base] = h0; Kh[base + 1] = h1;
            Kl[base] = lo0; Kl[base + 1] = lo1;
            split_pack(vv.x, vv.y, h0, lo0);
            split_pack(vv.z, vv.w, h1, lo1);
            Vh[base] = h0; Vh[base + 1] = h1;
            Vl[base] = lo0; Vl[base + 1] = lo1;
        }
        __syncthreads();

        if (j0 > rowbase + 15) continue;  // tile fully above diagonal for this warp

        // ---- scores = Q K^T (64 cols) ----
        float s[8][4];
        #pragma unroll
        for (int nf = 0; nf < 8; nf++)
            #pragma unroll
            for (int c = 0; c < 4; c++) s[nf][c] = 0.f;

        #pragma unroll
        for (int kt = 0; kt < 8; kt++) {
            unsigned qh[4], ql[4];
            unsigned qoff = (unsigned)((wid * 16 + l15) * (AST * 4) + (kt * 16 + lHi8) * 2);
            LDSM4(qh[0], qh[1], qh[2], qh[3], qBaseH + qoff);
            LDSM4(ql[0], ql[1], ql[2], ql[3], qBaseL + qoff);
            int kdd = kt * 16 + kDimOff;
            #pragma unroll
            for (int g2 = 0; g2 < 4; g2++) {
                unsigned koff = (unsigned)((g2 * 16 + kKey) * (AST * 4) + kdd * 2);
                unsigned kh0, kh1, kh2, kh3, klo0, klo1, klo2, klo3;
                LDSM4(kh0, kh1, kh2, kh3, kBaseH + koff);
                LDSM4(klo0, klo1, klo2, klo3, kBaseL + koff);
                int n0 = 2 * g2, n1 = 2 * g2 + 1;
                MMA_BF16(s[n0][0], s[n0][1], s[n0][2], s[n0][3],
                         ql[0], ql[1], ql[2], ql[3], kh0, kh1);
                MMA_BF16(s[n0][0], s[n0][1], s[n0][2], s[n0][3],
                         qh[0], qh[1], qh[2], qh[3], klo0, klo1);
                MMA_BF16(s[n0][0], s[n0][1], s[n0][2], s[n0][3],
                         qh[0], qh[1], qh[2], qh[3], kh0, kh1);
                MMA_BF16(s[n1][0], s[n1][1], s[n1][2], s[n1][3],
                         ql[0], ql[1], ql[2], ql[3], kh2, kh3);
                MMA_BF16(s[n1][0], s[n1][1], s[n1][2], s[n1][3],
                         qh[0], qh[1], qh[2], qh[3], klo2, klo3);
                MMA_BF16(s[n1][0], s[n1][1], s[n1][2], s[n1][3],
                         qh[0], qh[1], qh[2], qh[3], kh2, kh3);
            }
        }

        // ---- causal mask ----
        int r0 = rowbase + gid, r1 = r0 + 8;
        if (j0 + AKT - 1 > rowbase) {
            #pragma unroll
            for (int nf = 0; nf < 8; nf++) {
                int c0 = j0 + nf * 8 + 2 * tgid;
                if (c0 > r0)     s[nf][0] = -1e30f;
                if (c0 + 1 > r0) s[nf][1] = -1e30f;
                if (c0 > r1)     s[nf][2] = -1e30f;
                if (c0 + 1 > r1) s[nf][3] = -1e30f;
            }
        }

        // ---- warp-local online softmax (rows r0, r1) ----
        float t0 = -1e30f, t1 = -1e30f;
        #pragma unroll
        for (int nf = 0; nf < 8; nf++) {
            t0 = fmaxf(t0, fmaxf(s[nf][0], s[nf][1]));
            t1 = fmaxf(t1, fmaxf(s[nf][2], s[nf][3]));
        }
        t0 = fmaxf(t0, __shfl_xor_sync(0xffffffffu, t0, 1));
        t0 = fmaxf(t0, __shfl_xor_sync(0xffffffffu, t0, 2));
        t1 = fmaxf(t1, __shfl_xor_sync(0xffffffffu, t1, 1));
        t1 = fmaxf(t1, __shfl_xor_sync(0xffffffffu, t1, 2));
        float mn0 = fmaxf(m0, t0), mn1 = fmaxf(m1, t1);
        float a0 = __expf(m0 - mn0), a1 = __expf(m1 - mn1);
        m0 = mn0; m1 = mn1;
        float rs0 = 0.f, rs1 = 0.f;
        #pragma unroll
        for (int nf = 0; nf < 8; nf++) {
            s[nf][0] = __expf(s[nf][0] - mn0);
            s[nf][1] = __expf(s[nf][1] - mn0);
            s[nf][2] = __expf(s[nf][2] - mn1);
            s[nf][3] = __expf(s[nf][3] - mn1);
            rs0 += s[nf][0] + s[nf][1];
            rs1 += s[nf][2] + s[nf][3];
        }
        rs0 += __shfl_xor_sync(0xffffffffu, rs0, 1);
        rs0 += __shfl_xor_sync(0xffffffffu, rs0, 2);
        rs1 += __shfl_xor_sync(0xffffffffu, rs1, 1);
        rs1 += __shfl_xor_sync(0xffffffffu, rs1, 2);
        l0r = l0r * a0 + rs0;
        l1r = l1r * a1 + rs1;
        #pragma unroll
        for (int nv = 0; nv < 16; nv++) {
            oacc[nv][0] *= a0; oacc[nv][1] *= a0;
            oacc[nv][2] *= a1; oacc[nv][3] *= a1;
        }

        // ---- o += P V ----
        #pragma unroll
        for (int t = 0; t < 4; t++) {
            unsigned ph[4], pl[4];
            split_pack(s[2 * t][0],     s[2 * t][1],     ph[0], pl[0]);
            split_pack(s[2 * t][2],     s[2 * t][3],     ph[1], pl[1]);
            split_pack(s[2 * t + 1][0], s[2 * t + 1][1], ph[2], pl[2]);
            split_pack(s[2 * t + 1][2], s[2 * t + 1][3], ph[3], pl[3]);
            unsigned vf[16][2];
            int krow = t * 16 + l15;
            #pragma unroll
            for (int np = 0; np < 8; np++) {
                unsigned voff = (unsigned)(krow * (AST * 4) + (np * 16 + lHi8) * 2);
                LDSM4T(vf[2 * np][0], vf[2 * np][1], vf[2 * np + 1][0], vf[2 * np + 1][1],
                       vBaseH + voff);
            }
            #pragma unroll
            for (int nv = 0; nv < 16; nv++) {
                MMA_BF16(oacc[nv][0], oacc[nv][1], oacc[nv][2], oacc[nv][3],
                         pl[0], pl[1], pl[2], pl[3], vf[nv][0], vf[nv][1]);
                MMA_BF16(oacc[nv][0], oacc[nv][1], oacc[nv][2], oacc[nv][3],
                         ph[0], ph[1], ph[2], ph[3], vf[nv][0], vf[nv][1]);
            }
            #pragma unroll
            for (int np = 0; np < 8; np++) {
                unsigned voff = (unsigned)(krow * (AST * 4) + (np * 16 + lHi8) * 2);
                LDSM4T(vf[2 * np][0], vf[2 * np][1], vf[2 * np + 1][0], vf[2 * np + 1][1],
                       vBaseL + voff);
            }
            #pragma unroll
            for (int nv = 0; nv < 16; nv++) {
                MMA_BF16(oacc[nv][0], oacc[nv][1], oacc[nv][2], oacc[nv][3],
                         ph[0], ph[1], ph[2], ph[3], vf[nv][0], vf[nv][1]);
            }
        }
    }

    // ---- write out ----
    int r0 = rowbase + gid, r1 = r0 + 8;
    float il0 = 1.f / l0r, il1 = 1.f / l1r;
    #pragma unroll
    for (int nv = 0; nv < 16; nv++) {
        int col = nv * 8 + 2 * tgid;
        float* p0 = o + (((size_t)(b * SS + r0)) * HQ + h) * HD + col;
        float* p1 = o + (((size_t)(b * SS + r1)) * HQ + h) * HD + col;
        p0[0] = oacc[nv][0] * il0; p0[1] = oacc[nv][1] * il0;
        p1[0] = oacc[nv][2] * il1; p1[1] = oacc[nv][3] * il1;
    }
}

// ================= 3xTF32 GEMM (precision path: QKV only) =================
#define ASTRIDE 36
#define BSTRIDE 136
#define A_PLANE (128 * ASTRIDE)
#define B_PLANE (32 * BSTRIDE)
#define GEMM_SMEM_BYTES ((2 * A_PLANE + 2 * B_PLANE) * 4)

__global__ void __launch_bounds__(256)
mma_gemm_kernel(const float* __restrict__ A,
                const float* __restrict__ B,
                float* __restrict__ C,
                int M, int N, int K,
                const int* __restrict__ aIdx,
                const int* __restrict__ cIdx,
                const int* __restrict__ mCnt,
                const float* __restrict__ combine, int expert)
{
    int Meff = M;
    if (mCnt) Meff = min(M, *mCnt);
    int bm = blockIdx.y * 128;
    int bn = blockIdx.x * 128;
    if (bm >= Meff) return;

    extern __shared__ unsigned smem[];
    unsigned* AsH = smem;
    unsigned* AsL = AsH + A_PLANE;
    unsigned* BsH = AsL + A_PLANE;
    unsigned* BsL = BsH + B_PLANE;

    int tid = threadIdx.x;
    int wid = tid >> 5;
    int lane = tid & 31;
    int gid = lane >> 2;
    int tgid = lane & 3;
    int wm = (wid & 3) * 32;
    int wn = (wid >> 2) * 64;

    int a_m = tid >> 3;
    int a_kq = tid & 7;
    int b_k = tid >> 5;
    int b_f4 = tid & 31;

    float acc[2][8][4];
    #pragma unroll
    for (int i = 0; i < 2; i++)
        #pragma unroll
        for (int j = 0; j < 8; j++)
            #pragma unroll
            for (int c = 0; c < 4; c++) acc[i][j][c] = 0.f;

    for (int k0 = 0; k0 < K; k0 += 32) {
        #pragma unroll
        for (int p = 0; p < 4; p++) {
            int m = a_m + 32 * p;
            int gr = bm + m;
            float4 va = make_float4(0.f, 0.f, 0.f, 0.f);
            if (gr < Meff) {
                int ar = aIdx ? aIdx[gr] : gr;
                va = *reinterpret_cast<const float4*>(A + (size_t)ar * K + k0 + a_kq * 4);
            }
            int base = m * ASTRIDE + a_kq * 4;
            float vv[4] = {va.x, va.y, va.z, va.w};
            #pragma unroll
            for (int c = 0; c < 4; c++) {
                unsigned hi = f2tf32(vv[c]);
                AsH[base + c] = hi;
                AsL[base + c] = f2tf32(vv[c] - __uint_as_float(hi));
            }
        }
        #pragma unroll
        for (int p = 0; p < 4; p++) {
            int kk = b_k + 8 * p;
            float4 vb = *reinterpret_cast<const float4*>(B + (size_t)(k0 + kk) * N + bn + b_f4 * 4);
            int base = kk * BSTRIDE + b_f4 * 4;
            float vv[4] = {vb.x, vb.y, vb.z, vb.w};
            #pragma unroll
            for (int c = 0; c < 4; c++) {
                unsigned hi = f2tf32(vv[c]);
                BsH[base + c] = hi;
                BsL[base + c] = f2tf32(vv[c] - __uint_as_float(hi));
            }
        }
        __syncthreads();

        #pragma unroll
        for (int ks = 0; ks < 4; ks++) {
            int kk = ks * 8;
            unsigned afH[2][4], afL[2][4];
            #pragma unroll
            for (int mf = 0; mf < 2; mf++) {
                int mrow = wm + mf * 16 + gid;
                int i0 = mrow * ASTRIDE + kk + tgid;
                int i1 = (mrow + 8) * ASTRIDE + kk + tgid;
                afH[mf][0] = AsH[i0];     afL[mf][0] = AsL[i0];
                afH[mf][1] = AsH[i1];     afL[mf][1] = AsL[i1];
                afH[mf][2] = AsH[i0 + 4]; afL[mf][2] = AsL[i0 + 4];
                afH[mf][3] = AsH[i1 + 4]; afL[mf][3] = AsL[i1 + 4];
            }
            unsigned bfH[8][2], bfL[8][2];
            #pragma unroll
            for (int nf = 0; nf < 8; nf++) {
                int ncol = wn + nf * 8 + gid;
                int i0 = (kk + tgid) * BSTRIDE + ncol;
                int i1 = (kk + tgid + 4) * BSTRIDE + ncol;
                bfH[nf][0] = BsH[i0]; bfL[nf][0] = BsL[i0];
                bfH[nf][1] = BsH[i1]; bfL[nf][1] = BsL[i1];
            }
            #pragma unroll
            for (int mf = 0; mf < 2; mf++)
                #pragma unroll
                for (int nf = 0; nf < 8; nf++) {
                    asm volatile(
                        "mma.sync.aligned.m16n8k8.row.col.f32.tf32.tf32.f32 "
                        "{%0,%1,%2,%3}, {%4,%5,%6,%7}, {%8,%9}, {%0,%1,%2,%3};"
                        : "+f"(acc[mf][nf][0]), "+f"(acc[mf][nf][1]),
                          "+f"(acc[mf][nf][2]), "+f"(acc[mf][nf][3])
                        : "r"(afH[mf][0]), "r"(afH[mf][1]),
                          "r"(afH[mf][2]), "r"(afH[mf][3]),
                          "r"(bfL[nf][0]), "r"(bfL[nf][1]));
                    asm volatile(
                        "mma.sync.aligned.m16n8k8.row.col.f32.tf32.tf32.f32 "
                        "{%0,%1,%2,%3}, {%4,%5,%6,%7}, {%8,%9}, {%0,%1,%2,%3};"
                        : "+f"(acc[mf][nf][0]), "+f"(acc[mf][nf][1]),
                          "+f"(acc[mf][nf][2]), "+f"(acc[mf][nf][3])
                        : "r"(afL[mf][0]), "r"(afL[mf][1]),
                          "r"(afL[mf][2]), "r"(afL[mf][3]),
                          "r"(bfH[nf][0]), "r"(bfH[nf][1]));
                    asm volatile(
                        "mma.sync.aligned.m16n8k8.row.col.f32.tf32.tf32.f32 "
                        "{%0,%1,%2,%3}, {%4,%5,%6,%7}, {%8,%9}, {%0,%1,%2,%3};"
                        : "+f"(acc[mf][nf][0]), "+f"(acc[mf][nf][1]),
                          "+f"(acc[mf][nf][2]), "+f"(acc[mf][nf][3])
                        : "r"(afH[mf][0]), "r"(afH[mf][1]),
                          "r"(afH[mf][2]), "r"(afH[mf][3]),
                          "r"(bfH[nf][0]), "r"(bfH[nf][1]));
                }
        }
        __syncthreads();
    }

    #pragma unroll
    for (int mf = 0; mf < 2; mf++) {
        #pragma unroll
        for (int half = 0; half < 2; half++) {
            int row = bm + wm + mf * 16 + gid + half * 8;
            if (row >= Meff) continue;
            int crow = cIdx ? cIdx[row] : row;
            float w = 1.f;
            if (combine) w = combine[crow * EE + expert];
            #pragma unroll
            for (int nf = 0; nf < 8; nf++) {
                int col = bn + wn + nf * 8 + 2 * tgid;
                float v0 = acc[mf][nf][half * 2 + 0];
                float v1 = acc[mf][nf][half * 2 + 1];
                float* cp = C + (size_t)crow * N + col;
                if (combine) {
                    cp[0] += w * v0;
                    cp[1] += w * v1;
                } else {
                    cp[0] = v0;
                    cp[1] = v1;
                }
            }
        }
    }
}

// ================= bf16x2 GEMM (bulk path) =================
#define BAST 20
#define BBST 68

__global__ void __launch_bounds__(256, 2)
bf16_gemm_kernel(const float* __restrict__ A,
                 const float* __restrict__ B,
                 float* __restrict__ C,
                 int M, int N, int K,
                 const int* __restrict__ aIdx,
                 const int* __restrict__ cIdx,
                 const int* __restrict__ mCnt,
                 const float* __restrict__ combine, int expert)
{
    int Meff = M;
    if (mCnt) Meff = min(M, *mCnt);
    int bm = blockIdx.y * 128;
    int bn = blockIdx.x * 128;
    if (bm >= Meff) return;

    __shared__ unsigned AsH[128 * BAST];
    __shared__ unsigned AsL[128 * BAST];
    __shared__ unsigned BsH[32 * BBST];
    __shared__ unsigned BsL[32 * BBST];

    int tid = threadIdx.x;
    int wid = tid >> 5;
    int lane = tid & 31;
    int gid = lane >> 2;
    int tgid = lane & 3;
    int wm = (wid & 3) * 32;
    int wn = (wid >> 2) * 64;

    int a_m = tid >> 3;
    int a_kq = tid & 7;
    int b_k = tid >> 5;
    int b_f4 = tid & 31;

    unsigned aBaseH = (unsigned)__cvta_generic_to_shared(AsH);
    unsigned aBaseL = (unsigned)__cvta_generic_to_shared(AsL);
    unsigned bBaseH = (unsigned)__cvta_generic_to_shared(BsH);
    unsigned bBaseL = (unsigned)__cvta_generic_to_shared(BsL);
    int l15 = lane & 15;
    int lHi8 = (lane >> 4) << 3;

    float acc[2][8][4];
    #pragma unroll
    for (int i = 0; i < 2; i++)
        #pragma unroll
        for (int j = 0; j < 8; j++)
            #pragma unroll
            for (int c = 0; c < 4; c++) acc[i][j][c] = 0.f;

    for (int k0 = 0; k0 < K; k0 += 32) {
        #pragma unroll
        for (int p = 0; p < 4; p++) {
            int m = a_m + 32 * p;
            int gr = bm + m;
            float4 va = make_float4(0.f, 0.f, 0.f, 0.f);
            if (gr < Meff) {
                int ar = aIdx ? aIdx[gr] : gr;
                va = *reinterpret_cast<const float4*>(A + (size_t)ar * K + k0 + a_kq * 4);
            }
            int base = m * BAST + 2 * a_kq;
            unsigned h0, l0, h1, l1;
            split_pack(va.x, va.y, h0, l0);
            split_pack(va.z, va.w, h1, l1);
            AsH[base] = h0; AsH[base + 1] = h1;
            AsL[base] = l0; AsL[base + 1] = l1;
        }
        #pragma unroll
        for (int p = 0; p < 4; p++) {
            int kk = b_k + 8 * p;
            float4 vb = *reinterpret_cast<const float4*>(B + (size_t)(k0 + kk) * N + bn + b_f4 * 4);
            int base = kk * BBST + 2 * b_f4;
            unsigned h0, l0, h1, l1;
            split_pack(vb.x, vb.y, h0, l0);
            split_pack(vb.z, vb.w, h1, l1);
            BsH[base] = h0; BsH[base + 1] = h1;
            BsL[base] = l0; BsL[base + 1] = l1;
        }
        __syncthreads();

        #pragma unroll
        for (int ks = 0; ks < 2; ks++) {
            int kk = ks * 16;
            unsigned ah[2][4], al[2][4];
            #pragma unroll
            for (int mf = 0; mf < 2; mf++) {
                int mrow = wm + mf * 16 + l15;
                unsigned off = (unsigned)(mrow * (BAST * 4) + (kk + lHi8) * 2);
                LDSM4(ah[mf][0], ah[mf][1], ah[mf][2], ah[mf][3], aBaseH + off);
                LDSM4(al[mf][0], al[mf][1], al[mf][2], al[mf][3], aBaseL + off);
            }
            unsigned bfr[8][2];
            {
                int krow = kk + l15;
                #pragma unroll
                for (int nfp = 0; nfp < 4; nfp++) {
                    int ncol = wn + nfp * 16 + lHi8;
                    unsigned off = (unsigned)(krow * (BBST * 4) + ncol * 2);
                    LDSM4T(bfr[2 * nfp][0], bfr[2 * nfp][1],
                           bfr[2 * nfp + 1][0], bfr[2 * nfp + 1][1], bBaseH + off);
                }
            }
            #pragma unroll
            for (int mf = 0; mf < 2; mf++)
                #pragma unroll
                for (int nf = 0; nf < 8; nf++) {
                    MMA_BF16(acc[mf][nf][0], acc[mf][nf][1], acc[mf][nf][2], acc[mf][nf][3],
                             ah[mf][0], ah[mf][1], ah[mf][2], ah[mf][3],
                             bfr[nf][0], bfr[nf][1]);
                    MMA_BF16(acc[mf][nf][0], acc[mf][nf][1], acc[mf][nf][2], acc[mf][nf][3],
                             al[mf][0], al[mf][1], al[mf][2], al[mf][3],
                             bfr[nf][0], bfr[nf][1]);
                }
            {
                int krow = kk + l15;
                #pragma unroll
                for (int nfp = 0; nfp < 4; nfp++) {
                    int ncol = wn + nfp * 16 + lHi8;
                    unsigned off = (unsigned)(krow * (BBST * 4) + ncol * 2);
                    LDSM4T(bfr[2 * nfp][0], bfr[2 * nfp][1],
                           bfr[2 * nfp + 1][0], bfr[2 * nfp + 1][1], bBaseL + off);
                }
            }
            #pragma unroll
            for (int mf = 0; mf < 2; mf++)
                #pragma unroll
                for (int nf = 0; nf < 8; nf++) {
                    MMA_BF16(acc[mf][nf][0], acc[mf][nf][1], acc[mf][nf][2], acc[mf][nf][3],
                             ah[mf][0], ah[mf][1], ah[mf][2], ah[mf][3],
                             bfr[nf][0], bfr[nf][1]);
                }
        }
        __syncthreads();
    }

    #pragma unroll
    for (int mf = 0; mf < 2; mf++) {
        #pragma unroll
        for (int half = 0; half < 2; half++) {
            int row = bm + wm + mf * 16 + gid + half * 8;
            if (row >= Meff) continue;
            int crow = cIdx ? cIdx[row] : row;
            float w = 1.f;
            if (combine) w = combine[crow * EE + expert];
            #pragma unroll
            for (int nf = 0; nf < 8; nf++) {
                int col = bn + wn + nf * 8 + 2 * tgid;
                float v0 = acc[mf][nf][half * 2 + 0];
                float v1 = acc[mf][nf][half * 2 + 1];
                float* cp = C + (size_t)crow * N + col;
                if (combine) {
                    cp[0] += w * v0;
                    cp[1] += w * v1;
                } else {
                    cp[0] = v0;
                    cp[1] = v1;
                }
            }
        }
    }
}

// ---------------- elementwise gated GELU ----------------
__global__ void gelumul_kernel(float* __restrict__ g0, const float* __restrict__ g1,
                               size_t n, const int* __restrict__ cntPtr, int perRow)
{
    size_t i = (size_t)blockIdx.x * blockDim.x + threadIdx.x;
    size_t lim = cntPtr ? (size_t)(*cntPtr) * (size_t)perRow : n;
    if (i < lim) {
        float a = g0[i];
        g0[i] = gelu_tanh(a) * g1[i];
    }
}

// ---------------- router ----------------
__global__ void router_kernel(const float* __restrict__ gin,
                              const float* __restrict__ wg,
                              float* __restrict__ combine,
                              int* __restrict__ cnt,
                              int* __restrict__ idx,
                              float* __restrict__ psum)
{
    int tok = blockIdx.x;
    int tid = threadIdx.x;
    float s[EE] = {};
    const float* g = gin + (size_t)tok * DD;
    for (int d = tid; d < DD; d += 256) {
        float gv = g[d];
        const float* w = wg + d * EE;
        #pragma unroll
        for (int e = 0; e < EE; e++) s[e] += gv * w[e];
    }
    __shared__ float sh[256][EE];
    #pragma unroll
    for (int e = 0; e < EE; e++) sh[tid][e] = s[e];
    __syncthreads();
    for (int str = 128; str > 0; str >>= 1) {
        if (tid < str) {
            #pragma unroll
            for (int e = 0; e < EE; e++) sh[tid][e] += sh[tid + str][e];
        }
        __syncthreads();
    }
    if (tid == 0) {
        float lg[EE], pe[EE];
        float mx = -FLT_MAX;
        #pragma unroll
        for (int e = 0; e < EE; e++) { lg[e] = sh[0][e]; mx = fmaxf(mx, lg[e]); }
        float sum = 0.f;
        #pragma unroll
        for (int e = 0; e < EE; e++) { pe[e] = expf(lg[e] - mx); sum += pe[e]; }
        float inv = 1.0f / sum;
        #pragma unroll
        for (int e = 0; e < EE; e++) { pe[e] *= inv; atomicAdd(&psum[e], pe[e]); }
        int i0 = 0;
        #pragma unroll
        for (int e = 1; e < EE; e++) if (pe[e] > pe[i0]) i0 = e;
        int i1 = (i0 == 0) ? 1 : 0;
        #pragma unroll
        for (int e = 0; e < EE; e++) if (e != i0 && e != i1 && pe[e] > pe[i1]) i1 = e;
        float tot = pe[i0] + pe[i1];
        float w0 = pe[i0] / tot, w1 = pe[i1] / tot;
        float* crow = combine + (size_t)tok * EE;
        #pragma unroll
        for (int e = 0; e < EE; e++) crow[e] = 0.f;
        crow[i0] = w0; crow[i1] = w1;
        int p0 = atomicAdd(&cnt[i0], 1); idx[i0 * TT + p0] = tok;
        int p1 = atomicAdd(&cnt[i1], 1); idx[i1 * TT + p1] = tok;
    }
}

// ---------------- load-balance loss ----------------
__global__ void lb_kernel(const int* __restrict__ cnt, const float* __restrict__ psum,
                          float* __restrict__ out)
{
    float lb = 0.f;
    #pragma unroll
    for (int e = 0; e < EE; e++)
        lb += ((float)cnt[e] / (float)TT) * (psum[e] / (float)TT);
    out[0] = lb * ((float)(EE * EE) / (float)EE);
}

// ==================== host launcher ====================
extern "C" void kernel_launch(void* const* d_in, const int* in_sizes, int n_in,
                              void* d_out, int out_size)
{
    const int*   positions       = (const int*)  d_in[0];
    const float* x               = (const float*)d_in[1];
    const float* pre_attn_scale  = (const float*)d_in[2];
    const float* wq              = (const float*)d_in[3];
    const float* wk              = (const float*)d_in[4];
    const float* wv              = (const float*)d_in[5];
    const float* wo              = (const float*)d_in[6];
    const float* q_norm_scale    = (const float*)d_in[7];
    const float* k_norm_scale    = (const float*)d_in[8];
    const float* v_norm_scale    = (const float*)d_in[9];
    const float* post_attn_scale = (const float*)d_in[10];
    const float* pre_ffw_scale   = (const float*)d_in[11];
    const float* shared_wi0      = (const float*)d_in[12];
    const float* shared_wi1      = (const float*)d_in[13];
    const float* shared_wo       = (const float*)d_in[14];
    const float* post_ff1_scale  = (const float*)d_in[15];
    const float* pre_ff2_scale   = (const float*)d_in[16];
    const float* router_scale    = (const float*)d_in[17];
    const float* w_gate          = (const float*)d_in[18];
    const float* ewi0            = (const float*)d_in[19];
    const float* ewi1            = (const float*)d_in[20];
    const float* ewo             = (const float*)d_in[21];
    const float* post_ff2_scale  = (const float*)d_in[22];
    const float* layer_scalar    = (const float*)d_in[23];
    float* out = (float*)d_out;

    static int smemConfigured = 0;
    if (!smemConfigured) {
        cudaFuncSetAttribute(mma_gemm_kernel,
                             cudaFuncAttributeMaxDynamicSharedMemorySize,
                             GEMM_SMEM_BYTES);
        cudaFuncSetAttribute(fattn_kernel,
                             cudaFuncAttributeMaxDynamicSharedMemorySize,
                             ATT_SMEM_BYTES);
        smemConfigured = 1;
    }

    float* sc = nullptr;
    int*   isc = nullptr;
    cudaGetSymbolAddress((void**)&sc, g_scratch);
    cudaGetSymbolAddress((void**)&isc, g_iscratch);

    float* lnx   = sc + OFF_LNX;
    float* qb    = sc + OFF_Q;
    float* kb    = sc + OFF_K;
    float* vb    = sc + OFF_V;
    float* ob    = sc + OFF_O;
    float* attnb = sc + OFF_ATTN;
    float* hb    = sc + OFF_H;
    float* ffin  = sc + OFF_FFIN;
    float* g0    = sc + OFF_G0;
    float* g1    = sc + OFF_G1;
    float* shb   = sc + OFF_SH;
    float* rin   = sc + OFF_RIN;
    float* gin   = sc + OFF_GIN;
    float* routb = sc + OFF_ROUT;
    float* comb  = sc + OFF_COMB;
    float* eg0   = sc + OFF_EG0;
    float* eg1   = sc + OFF_EG1;
    float* psum  = sc + OFF_PSUM;
    int* idx = isc;
    int* cnt = isc + EE * TT;

    auto gemm_hi = [&](const float* A, const float* Bm, float* C, int M, int N, int K) {
        dim3 grid(N / 128, (M + 127) / 128);
        mma_gemm_kernel<<<grid, 256, GEMM_SMEM_BYTES>>>(A, Bm, C, M, N, K,
                                                        nullptr, nullptr, nullptr, nullptr, 0);
    };
    auto gemm_bf = [&](const float* A, const float* Bm, float* C, int M, int N, int K,
                       const int* aIdx, const int* cIdx, const int* mc,
                       const float* cw, int ex) {
        dim3 grid(N / 128, (M + 127) / 128);
        bf16_gemm_kernel<<<grid, 256>>>(A, Bm, C, M, N, K, aIdx, cIdx, mc, cw, ex);
    };

    // 1) pre-attn norm
    rms_kernel<<<TT, 256>>>(x, pre_attn_scale, 1.f, nullptr, nullptr, nullptr, lnx);

    // 2) QKV projections (high precision: feeds unscaled QK^T)
    gemm_hi(lnx, wq, qb, TT, HQ * HD, DD);
    gemm_hi(lnx, wk, kb, TT, HKV * HD, DD);
    gemm_hi(lnx, wv, vb, TT, HKV * HD, DD);

    // 3) per-head norms + rope
    head_norm_rope_kernel<<<TT * HQ, HD>>>(qb, q_norm_scale, positions, HQ, 1);
    head_norm_rope_kernel<<<TT * HKV, HD>>>(kb, k_norm_scale, positions, HKV, 1);
    head_norm_rope_kernel<<<TT * HKV, HD>>>(vb, v_norm_scale, positions, HKV, 0);

    // 4) attention (tensor-core flash)
    {
        dim3 grid(SS / ATQ, HQ, BB);
        fattn_kernel<<<grid, 256, ATT_SMEM_BYTES>>>(qb, kb, vb, ob);
    }

    // 5) output projection + post-attn norm + residual
    gemm_bf(ob, wo, attnb, TT, DD, HQ * HD, nullptr, nullptr, nullptr, nullptr, 0);
    rms_kernel<<<TT, 256>>>(attnb, post_attn_scale, 1.f, x, nullptr, nullptr, hb);

    // 6) shared FFN
    rms_kernel<<<TT, 256>>>(hb, pre_ffw_scale, 1.f, nullptr, nullptr, nullptr, ffin);
    gemm_bf(ffin, shared_wi0, g0, TT, FS, DD, nullptr, nullptr, nullptr, nullptr, 0);
    gemm_bf(ffin, shared_wi1, g1, TT, FS, DD, nullptr, nullptr, nullptr, nullptr, 0);
    gelumul_kernel<<<(unsigned)(SZ_TFS / 256), 256>>>(g0, g1, SZ_TFS, nullptr, 0);
    gemm_bf(g0, shared_wo, shb, TT, DD, FS, nullptr, nullptr, nullptr, nullptr, 0);
    rms_kernel<<<TT, 256>>>(shb, post_ff1_scale, 1.f, nullptr, nullptr, nullptr, shb);

    // 7) router inputs
    rms_kernel<<<TT, 256>>>(hb, pre_ff2_scale, 1.f, nullptr, nullptr, nullptr, rin);
    rms_kernel<<<TT, 256>>>(hb, router_scale, 0.02209708691207961f /*D^-0.5*/,
                            nullptr, nullptr, nullptr, gin);

    // 8) router + MoE dispatch
    cudaMemsetAsync(cnt, 0, EE * sizeof(int));
    cudaMemsetAsync(psum, 0, EE * sizeof(float));
    cudaMemsetAsync(routb, 0, SZ_TD * sizeof(float));
    router_kernel<<<TT, 256>>>(gin, w_gate, comb, cnt, idx, psum);

    for (int e = 0; e < EE; e++) {
        const int* eidx = idx + e * TT;
        const int* ecnt = cnt + e;
        const float* bwi0 = ewi0 + (size_t)e * DD * FE;
        const float* bwi1 = ewi1 + (size_t)e * DD * FE;
        const float* bwo  = ewo  + (size_t)e * FE * DD;
        gemm_bf(rin, bwi0, eg0, TT, FE, DD, eidx, nullptr, ecnt, nullptr, 0);
        gemm_bf(rin, bwi1, eg1, TT, FE, DD, eidx, nullptr, ecnt, nullptr, 0);
        gelumul_kernel<<<(unsigned)(SZ_TFE / 256), 256>>>(eg0, eg1, SZ_TFE, ecnt, FE);
        gemm_bf(eg0, bwo, routb, TT, DD, FE, nullptr, eidx, ecnt, comb, e);
    }

    // 9) final combine
    rms_kernel<<<TT, 256>>>(routb, post_ff2_scale, 1.f, shb, hb, layer_scalar, out);

    // 10) lb loss
    if (out_size > TT * DD) {
        lb_kernel<<<1, 1>>>(cnt, psum, out + (size_t)TT * DD);
    }
}

// round 6
// speedup vs baseline: 5.8094x; 1.4698x over previous
#include <cuda_runtime.h>
#include <cuda_bf16.h>
#include <cfloat>
#include <math.h>

// ---------------- problem constants ----------------
#define BB 4
#define SS 1024
#define DD 2048
#define HQ 16
#define HKV 8
#define HD 128
#define GRP 2
#define EE 8
#define TOPK 2
#define FE 1024
#define FS 8192
#define TT (BB*SS)          // 4096 tokens
#define EPS 1e-6f

// ---------------- scratch layout (floats) ----------------
#define SZ_TD   ((size_t)TT*DD)
#define SZ_TKV  ((size_t)TT*HKV*HD)
#define SZ_TFS  ((size_t)TT*FS)
#define SZ_TFE  ((size_t)TT*FE)

#define OFF_LNX   ((size_t)0)
#define OFF_Q     (OFF_LNX  + SZ_TD)
#define OFF_K     (OFF_Q    + SZ_TD)
#define OFF_V     (OFF_K    + SZ_TKV)
#define OFF_O     (OFF_V    + SZ_TKV)
#define OFF_ATTN  (OFF_O    + SZ_TD)
#define OFF_H     (OFF_ATTN + SZ_TD)
#define OFF_FFIN  (OFF_H    + SZ_TD)
#define OFF_G0    (OFF_FFIN + SZ_TD)
#define OFF_EGALL (OFF_G0   + SZ_TFS)        // 8 * TT * FE == TT * FS floats
#define OFF_SH    (OFF_EGALL+ SZ_TFS)
#define OFF_RIN   (OFF_SH   + SZ_TD)
#define OFF_GIN   (OFF_RIN  + SZ_TD)
#define OFF_ROUT  (OFF_GIN  + SZ_TD)
#define OFF_COMB  (OFF_ROUT + SZ_TD)
#define OFF_PSUM  (OFF_COMB + (size_t)TT*EE)
#define SCRATCH_TOTAL (OFF_PSUM + 8)

__device__ float g_scratch[SCRATCH_TOTAL];
__device__ int   g_iscratch[EE*TT + EE];

// ---------------- helpers ----------------
__device__ __forceinline__ float gelu_tanh(float v) {
    const float c = 0.7978845608028654f;
    float u = c * (v + 0.044715f * v * v * v);
    return 0.5f * v * (1.0f + tanhf(u));
}
__device__ __forceinline__ unsigned pack_bf16(float x, float y) {
    __nv_bfloat162 t = __floats2bfloat162_rn(x, y);
    return *reinterpret_cast<unsigned*>(&t);
}
__device__ __forceinline__ void split_pack(float x, float y,
                                           unsigned &hiW, unsigned &loW0) {
    __nv_bfloat16 bx = __float2bfloat16_rn(x);
    __nv_bfloat16 by = __float2bfloat16_rn(y);
    float hx = __bfloat162float(bx);
    float hy = __bfloat162float(by);
    __nv_bfloat162 h2; h2.x = bx; h2.y = by;
    hiW = *reinterpret_cast<unsigned*>(&h2);
    loW0 = pack_bf16(x - hx, y - hy);
}

#define LDSM4(r0,r1,r2,r3,addr) \
    asm volatile("ldmatrix.sync.aligned.m8n8.x4.shared.b16 {%0,%1,%2,%3}, [%4];" \
                 : "=r"(r0),"=r"(r1),"=r"(r2),"=r"(r3) : "r"(addr))
#define LDSM4T(r0,r1,r2,r3,addr) \
    asm volatile("ldmatrix.sync.aligned.m8n8.x4.trans.shared.b16 {%0,%1,%2,%3}, [%4];" \
                 : "=r"(r0),"=r"(r1),"=r"(r2),"=r"(r3) : "r"(addr))
#define MMA_BF16(d0,d1,d2,d3,a0,a1,a2,a3,b0,b1) \
    asm volatile("mma.sync.aligned.m16n8k16.row.col.f32.bf16.bf16.f32 " \
                 "{%0,%1,%2,%3}, {%4,%5,%6,%7}, {%8,%9}, {%0,%1,%2,%3};" \
                 : "+f"(d0),"+f"(d1),"+f"(d2),"+f"(d3) \
                 : "r"(a0),"r"(a1),"r"(a2),"r"(a3),"r"(b0),"r"(b1))

// ---------------- RMS norm over D=2048, generic epilogue ----------------
__global__ void rms_kernel(const float* __restrict__ in,
                           const float* __restrict__ scale, float cmul,
                           const float* __restrict__ res1,
                           const float* __restrict__ res2,
                           const float* __restrict__ scalarPtr,
                           float* __restrict__ out)
{
    int row = blockIdx.x;
    int tid = threadIdx.x;
    const float* xr = in + (size_t)row * DD;
    float ss = 0.f;
    for (int d = tid; d < DD; d += 256) { float v = xr[d]; ss += v * v; }
    for (int o = 16; o > 0; o >>= 1) ss += __shfl_xor_sync(0xffffffffu, ss, o);
    __shared__ float wsum[8];
    if ((tid & 31) == 0) wsum[tid >> 5] = ss;
    __syncthreads();
    float tot = 0.f;
    #pragma unroll
    for (int w = 0; w < 8; w++) tot += wsum[w];
    float inv = rsqrtf(tot * (1.0f / DD) + EPS);
    float sc = scalarPtr ? *scalarPtr : 1.0f;
    for (int d = tid; d < DD; d += 256) {
        float y = xr[d] * inv;
        if (scale) y *= scale[d];
        y *= cmul;
        if (res1) y += res1[(size_t)row * DD + d];
        if (res2) y += res2[(size_t)row * DD + d];
        out[(size_t)row * DD + d] = y * sc;
    }
}

// ---------------- per-head RMS (+ optional RoPE), HD=128 ----------------
__global__ void head_norm_rope_kernel(float* __restrict__ data,
                                      const float* __restrict__ scale,
                                      const int* __restrict__ positions,
                                      int H, int doRope)
{
    int idx = blockIdx.x;
    int tid = threadIdx.x;
    int s = (idx / H) % SS;
    int b = idx / (H * SS);
    float* xr = data + (size_t)idx * HD;
    float v = xr[tid];
    float ss = v * v;
    for (int o = 16; o > 0; o >>= 1) ss += __shfl_xor_sync(0xffffffffu, ss, o);
    __shared__ float wsum[4];
    if ((tid & 31) == 0) wsum[tid >> 5] = ss;
    __syncthreads();
    float tot = wsum[0] + wsum[1] + wsum[2] + wsum[3];
    float y = v * rsqrtf(tot * (1.0f / HD) + EPS) * scale[tid];
    if (doRope) {
        __shared__ float tmp[HD];
        tmp[tid] = y;
        __syncthreads();
        int pos = positions[b * SS + s];
        int j = tid & 63;
        float inv = powf(10000.0f, -(float)j / 64.0f);
        float ang = (float)pos * inv;
        float sn, cs;
        sincosf(ang, &sn, &cs);
        float x1 = tmp[j], x2 = tmp[64 + j];
        y = (tid < 64) ? (x1 * cs - x2 * sn) : (x2 * cs + x1 * sn);
    }
    xr[tid] = y;
}

// ---------------- tensor-core flash attention ----------------
#define ATQ 128
#define AKT 64
#define AST 68
#define Q_WORDS (ATQ*AST)
#define KV_WORDS (AKT*AST)
#define ATT_SMEM_BYTES ((2*Q_WORDS + 4*KV_WORDS)*4)

__global__ void __launch_bounds__(256, 1)
fattn_kernel(const float* __restrict__ q,
             const float* __restrict__ k,
             const float* __restrict__ v,
             float* __restrict__ o)
{
    extern __shared__ unsigned att_smem[];
    unsigned* Qh = att_smem;
    unsigned* Ql = Qh + Q_WORDS;
    unsigned* Kh = Ql + Q_WORDS;
    unsigned* Kl = Kh + KV_WORDS;
    unsigned* Vh = Kl + KV_WORDS;
    unsigned* Vl = Vh + KV_WORDS;

    int b = blockIdx.z, h = blockIdx.y;
    int q0 = blockIdx.x * ATQ;
    int hkv = h / GRP;
    int tid = threadIdx.x, wid = tid >> 5, lane = tid & 31;
    int gid = lane >> 2, tgid = lane & 3;
    int l15 = lane & 15, lHi8 = (lane >> 4) << 3;

    unsigned qBaseH = (unsigned)__cvta_generic_to_shared(Qh);
    unsigned qBaseL = (unsigned)__cvta_generic_to_shared(Ql);
    unsigned kBaseH = (unsigned)__cvta_generic_to_shared(Kh);
    unsigned kBaseL = (unsigned)__cvta_generic_to_shared(Kl);
    unsigned vBaseH = (unsigned)__cvta_generic_to_shared(Vh);
    unsigned vBaseL = (unsigned)__cvta_generic_to_shared(Vl);

    for (int i = tid; i < ATQ * 32; i += 256) {
        int row = i >> 5, c4 = i & 31;
        float4 vq = *(const float4*)(q + (((size_t)(b * SS + q0 + row)) * HQ + h) * HD + 4 * c4);
        unsigned h0, l0, h1, l1;
        split_pack(vq.x, vq.y, h0, l0);
        split_pack(vq.z, vq.w, h1, l1);
        int base = row * AST + c4 * 2;
        Qh[base] = h0; Qh[base + 1] = h1;
        Ql[base] = l0; Ql[base + 1] = l1;
    }

    float oacc[16][4];
    #pragma unroll
    for (int i = 0; i < 16; i++)
        #pragma unroll
        for (int c = 0; c < 4; c++) oacc[i][c] = 0.f;
    float m0 = -1e30f, m1 = -1e30f, l0r = 0.f, l1r = 0.f;

    int rowbase = q0 + wid * 16;
    int kKey = (lane & 7) + ((lane >> 4) << 3);
    int kDimOff = (lane & 8) ? 8 : 0;

    int ntiles = (q0 >> 6) + 2;
    for (int jt = 0; jt < ntiles; jt++) {
        int j0 = jt * AKT;
        __syncthreads();
        for (int i = tid; i < AKT * 32; i += 256) {
            int row = i >> 5, c4 = i & 31;
            size_t gbase = (((size_t)(b * SS + j0 + row)) * HKV + hkv) * HD + 4 * c4;
            float4 vk = *(const float4*)(k + gbase);
            float4 vv = *(const float4*)(v + gbase);
            int base = row * AST + c4 * 2;
            unsigned h0, lo0, h1, lo1;
            split_pack(vk.x, vk.y, h0, lo0);
            split_pack(vk.z, vk.w, h1, lo1);
            Kh[base] = h0; Kh[base + 1] = h1;
            Kl[base] = lo0; Kl[base + 1] = lo1;
            split_pack(vv.x, vv.y, h0, lo0);
            split_pack(vv.z, vv.w, h1, lo1);
            Vh[base] = h0; Vh[base + 1] = h1;
            Vl[base] = lo0; Vl[base + 1] = lo1;
        }
        __syncthreads();

        if (j0 > rowbase + 15) continue;

        float s[8][4];
        #pragma unroll
        for (int nf = 0; nf < 8; nf++)
            #pragma unroll
            for (int c = 0; c < 4; c++) s[nf][c] = 0.f;

        #pragma unroll
        for (int kt = 0; kt < 8; kt++) {
            unsigned qh[4], ql[4];
            unsigned qoff = (unsigned)((wid * 16 + l15) * (AST * 4) + (kt * 16 + lHi8) * 2);
            LDSM4(qh[0], qh[1], qh[2], qh[3], qBaseH + qoff);
            LDSM4(ql[0], ql[1], ql[2], ql[3], qBaseL + qoff);
            int kdd = kt * 16 + kDimOff;
            #pragma unroll
            for (int g2 = 0; g2 < 4; g2++) {
                unsigned koff = (unsigned)((g2 * 16 + kKey) * (AST * 4) + kdd * 2);
                unsigned kh0, kh1, kh2, kh3, klo0, klo1, klo2, klo3;
                LDSM4(kh0, kh1, kh2, kh3, kBaseH + koff);
                LDSM4(klo0, klo1, klo2, klo3, kBaseL + koff);
                int n0 = 2 * g2, n1 = 2 * g2 + 1;
                MMA_BF16(s[n0][0], s[n0][1], s[n0][2], s[n0][3],
                         ql[0], ql[1], ql[2], ql[3], kh0, kh1);
                MMA_BF16(s[n0][0], s[n0][1], s[n0][2], s[n0][3],
                         qh[0], qh[1], qh[2], qh[3], klo0, klo1);
                MMA_BF16(s[n0][0], s[n0][1], s[n0][2], s[n0][3],
                         qh[0], qh[1], qh[2], qh[3], kh0, kh1);
                MMA_BF16(s[n1][0], s[n1][1], s[n1][2], s[n1][3],
                         ql[0], ql[1], ql[2], ql[3], kh2, kh3);
                MMA_BF16(s[n1][0], s[n1][1], s[n1][2], s[n1][3],
                         qh[0], qh[1], qh[2], qh[3], klo2, klo3);
                MMA_BF16(s[n1][0], s[n1][1], s[n1][2], s[n1][3],
                         qh[0], qh[1], qh[2], qh[3], kh2, kh3);
            }
        }

        int r0 = rowbase + gid, r1 = r0 + 8;
        if (j0 + AKT - 1 > rowbase) {
            #pragma unroll
            for (int nf = 0; nf < 8; nf++) {
                int c0 = j0 + nf * 8 + 2 * tgid;
                if (c0 > r0)     s[nf][0] = -1e30f;
                if (c0 + 1 > r0) s[nf][1] = -1e30f;
                if (c0 > r1)     s[nf][2] = -1e30f;
                if (c0 + 1 > r1) s[nf][3] = -1e30f;
            }
        }

        float t0 = -1e30f, t1 = -1e30f;
        #pragma unroll
        for (int nf = 0; nf < 8; nf++) {
            t0 = fmaxf(t0, fmaxf(s[nf][0], s[nf][1]));
            t1 = fmaxf(t1, fmaxf(s[nf][2], s[nf][3]));
        }
        t0 = fmaxf(t0, __shfl_xor_sync(0xffffffffu, t0, 1));
        t0 = fmaxf(t0, __shfl_xor_sync(0xffffffffu, t0, 2));
        t1 = fmaxf(t1, __shfl_xor_sync(0xffffffffu, t1, 1));
        t1 = fmaxf(t1, __shfl_xor_sync(0xffffffffu, t1, 2));
        float mn0 = fmaxf(m0, t0), mn1 = fmaxf(m1, t1);
        float a0 = __expf(m0 - mn0), a1 = __expf(m1 - mn1);
        m0 = mn0; m1 = mn1;
        float rs0 = 0.f, rs1 = 0.f;
        #pragma unroll
        for (int nf = 0; nf < 8; nf++) {
            s[nf][0] = __expf(s[nf][0] - mn0);
            s[nf][1] = __expf(s[nf][1] - mn0);
            s[nf][2] = __expf(s[nf][2] - mn1);
            s[nf][3] = __expf(s[nf][3] - mn1);
            rs0 += s[nf][0] + s[nf][1];
            rs1 += s[nf][2] + s[nf][3];
        }
        rs0 += __shfl_xor_sync(0xffffffffu, rs0, 1);
        rs0 += __shfl_xor_sync(0xffffffffu, rs0, 2);
        rs1 += __shfl_xor_sync(0xffffffffu, rs1, 1);
        rs1 += __shfl_xor_sync(0xffffffffu, rs1, 2);
        l0r = l0r * a0 + rs0;
        l1r = l1r * a1 + rs1;
        #pragma unroll
        for (int nv = 0; nv < 16; nv++) {
            oacc[nv][0] *= a0; oacc[nv][1] *= a0;
            oacc[nv][2] *= a1; oacc[nv][3] *= a1;
        }

        #pragma unroll
        for (int t = 0; t < 4; t++) {
            unsigned ph[4], pl[4];
            split_pack(s[2 * t][0],     s[2 * t][1],     ph[0], pl[0]);
            split_pack(s[2 * t][2],     s[2 * t][3],     ph[1], pl[1]);
            split_pack(s[2 * t + 1][0], s[2 * t + 1][1], ph[2], pl[2]);
            split_pack(s[2 * t + 1][2], s[2 * t + 1][3], ph[3], pl[3]);
            unsigned vf[16][2];
            int krow = t * 16 + l15;
            #pragma unroll
            for (int np = 0; np < 8; np++) {
                unsigned voff = (unsigned)(krow * (AST * 4) + (np * 16 + lHi8) * 2);
                LDSM4T(vf[2 * np][0], vf[2 * np][1], vf[2 * np + 1][0], vf[2 * np + 1][1],
                       vBaseH + voff);
            }
            #pragma unroll
            for (int nv = 0; nv < 16; nv++) {
                MMA_BF16(oacc[nv][0], oacc[nv][1], oacc[nv][2], oacc[nv][3],
                         pl[0], pl[1], pl[2], pl[3], vf[nv][0], vf[nv][1]);
                MMA_BF16(oacc[nv][0], oacc[nv][1], oacc[nv][2], oacc[nv][3],
                         ph[0], ph[1], ph[2], ph[3], vf[nv][0], vf[nv][1]);
            }
            #pragma unroll
            for (int np = 0; np < 8; np++) {
                unsigned voff = (unsigned)(krow * (AST * 4) + (np * 16 + lHi8) * 2);
                LDSM4T(vf[2 * np][0], vf[2 * np][1], vf[2 * np + 1][0], vf[2 * np + 1][1],
                       vBaseL + voff);
            }
            #pragma unroll
            for (int nv = 0; nv < 16; nv++) {
                MMA_BF16(oacc[nv][0], oacc[nv][1], oacc[nv][2], oacc[nv][3],
                         ph[0], ph[1], ph[2], ph[3], vf[nv][0], vf[nv][1]);
            }
        }
    }

    int r0 = rowbase + gid, r1 = r0 + 8;
    float il0 = 1.f / l0r, il1 = 1.f / l1r;
    #pragma unroll
    for (int nv = 0; nv < 16; nv++) {
        int col = nv * 8 + 2 * tgid;
        float* p0 = o + (((size_t)(b * SS + r0)) * HQ + h) * HD + col;
        float* p1 = o + (((size_t)(b * SS + r1)) * HQ + h) * HD + col;
        p0[0] = oacc[nv][0] * il0; p0[1] = oacc[nv][1] * il0;
        p1[0] = oacc[nv][2] * il1; p1[1] = oacc[nv][3] * il1;
    }
}

// ================= bf16x3 GEMM =================
// C = A*B (hi/lo split, 3 MMAs per k16). Optional per-z expert batching,
// gather-A / scatter-C with atomic combine.
#define BAST 20
#define BBST 68

__global__ void __launch_bounds__(256, 2)
bf16_gemm_kernel(const float* __restrict__ Ag,
                 const float* __restrict__ Bg,
                 float* __restrict__ C,
                 int M, int N, int K,
                 const int* __restrict__ aIdxg,
                 const int* __restrict__ cIdxg,
                 const int* __restrict__ cntg,
                 const float* __restrict__ combine,
                 size_t aZStr, size_t bZStr, int idxZStr)
{
    int z = blockIdx.z;
    const float* A = Ag + (size_t)z * aZStr;
    const float* B = Bg + (size_t)z * bZStr;
    const int* aIdx = aIdxg ? aIdxg + (size_t)z * idxZStr : nullptr;
    const int* cIdx = cIdxg ? cIdxg + (size_t)z * idxZStr : nullptr;
    int Meff = cntg ? min(M, cntg[z]) : M;
    int bm = blockIdx.y * 128;
    int bn = blockIdx.x * 128;
    if (bm >= Meff) return;

    __shared__ unsigned AsH[128 * BAST];
    __shared__ unsigned AsL[128 * BAST];
    __shared__ unsigned BsH[32 * BBST];
    __shared__ unsigned BsL[32 * BBST];

    int tid = threadIdx.x;
    int wid = tid >> 5;
    int lane = tid & 31;
    int gid = lane >> 2;
    int tgid = lane & 3;
    int wm = (wid & 3) * 32;
    int wn = (wid >> 2) * 64;

    int a_m = tid >> 3;
    int a_kq = tid & 7;
    int b_k = tid >> 5;
    int b_f4 = tid & 31;

    unsigned aBaseH = (unsigned)__cvta_generic_to_shared(AsH);
    unsigned aBaseL = (unsigned)__cvta_generic_to_shared(AsL);
    unsigned bBaseH = (unsigned)__cvta_generic_to_shared(BsH);
    unsigned bBaseL = (unsigned)__cvta_generic_to_shared(BsL);
    int l15 = lane & 15;
    int lHi8 = (lane >> 4) << 3;

    float acc[2][8][4];
    #pragma unroll
    for (int i = 0; i < 2; i++)
        #pragma unroll
        for (int j = 0; j < 8; j++)
            #pragma unroll
            for (int c = 0; c < 4; c++) acc[i][j][c] = 0.f;

    for (int k0 = 0; k0 < K; k0 += 32) {
        #pragma unroll
        for (int p = 0; p < 4; p++) {
            int m = a_m + 32 * p;
            int gr = bm + m;
            float4 va = make_float4(0.f, 0.f, 0.f, 0.f);
            if (gr < Meff) {
                int ar = aIdx ? aIdx[gr] : gr;
                va = *reinterpret_cast<const float4*>(A + (size_t)ar * K + k0 + a_kq * 4);
            }
            int base = m * BAST + 2 * a_kq;
            unsigned h0, l0, h1, l1;
            split_pack(va.x, va.y, h0, l0);
            split_pack(va.z, va.w, h1, l1);
            AsH[base] = h0; AsH[base + 1] = h1;
            AsL[base] = l0; AsL[base + 1] = l1;
        }
        #pragma unroll
        for (int p = 0; p < 4; p++) {
            int kk = b_k + 8 * p;
            float4 vb = *reinterpret_cast<const float4*>(B + (size_t)(k0 + kk) * N + bn + b_f4 * 4);
            int base = kk * BBST + 2 * b_f4;
            unsigned h0, l0, h1, l1;
            split_pack(vb.x, vb.y, h0, l0);
            split_pack(vb.z, vb.w, h1, l1);
            BsH[base] = h0; BsH[base + 1] = h1;
            BsL[base] = l0; BsL[base + 1] = l1;
        }
        __syncthreads();

        #pragma unroll
        for (int ks = 0; ks < 2; ks++) {
            int kk = ks * 16;
            unsigned ah[2][4], al[2][4];
            #pragma unroll
            for (int mf = 0; mf < 2; mf++) {
                int mrow = wm + mf * 16 + l15;
                unsigned off = (unsigned)(mrow * (BAST * 4) + (kk + lHi8) * 2);
                LDSM4(ah[mf][0], ah[mf][1], ah[mf][2], ah[mf][3], aBaseH + off);
                LDSM4(al[mf][0], al[mf][1], al[mf][2], al[mf][3], aBaseL + off);
            }
            unsigned bfr[8][2];
            {
                int krow = kk + l15;
                #pragma unroll
                for (int nfp = 0; nfp < 4; nfp++) {
                    int ncol = wn + nfp * 16 + lHi8;
                    unsigned off = (unsigned)(krow * (BBST * 4) + ncol * 2);
                    LDSM4T(bfr[2 * nfp][0], bfr[2 * nfp][1],
                           bfr[2 * nfp + 1][0], bfr[2 * nfp + 1][1], bBaseH + off);
                }
            }
            #pragma unroll
            for (int mf = 0; mf < 2; mf++)
                #pragma unroll
                for (int nf = 0; nf < 8; nf++) {
                    MMA_BF16(acc[mf][nf][0], acc[mf][nf][1], acc[mf][nf][2], acc[mf][nf][3],
                             ah[mf][0], ah[mf][1], ah[mf][2], ah[mf][3],
                             bfr[nf][0], bfr[nf][1]);
                    MMA_BF16(acc[mf][nf][0], acc[mf][nf][1], acc[mf][nf][2], acc[mf][nf][3],
                             al[mf][0], al[mf][1], al[mf][2], al[mf][3],
                             bfr[nf][0], bfr[nf][1]);
                }
            {
                int krow = kk + l15;
                #pragma unroll
                for (int nfp = 0; nfp < 4; nfp++) {
                    int ncol = wn + nfp * 16 + lHi8;
                    unsigned off = (unsigned)(krow * (BBST * 4) + ncol * 2);
                    LDSM4T(bfr[2 * nfp][0], bfr[2 * nfp][1],
                           bfr[2 * nfp + 1][0], bfr[2 * nfp + 1][1], bBaseL + off);
                }
            }
            #pragma unroll
            for (int mf = 0; mf < 2; mf++)
                #pragma unroll
                for (int nf = 0; nf < 8; nf++) {
                    MMA_BF16(acc[mf][nf][0], acc[mf][nf][1], acc[mf][nf][2], acc[mf][nf][3],
                             ah[mf][0], ah[mf][1], ah[mf][2], ah[mf][3],
                             bfr[nf][0], bfr[nf][1]);
                }
        }
        __syncthreads();
    }

    #pragma unroll
    for (int mf = 0; mf < 2; mf++) {
        #pragma unroll
        for (int half = 0; half < 2; half++) {
            int row = bm + wm + mf * 16 + gid + half * 8;
            if (row >= Meff) continue;
            int crow = cIdx ? cIdx[row] : row;
            float w = 1.f;
            if (combine) w = combine[crow * EE + z];
            #pragma unroll
            for (int nf = 0; nf < 8; nf++) {
                int col = bn + wn + nf * 8 + 2 * tgid;
                float v0 = acc[mf][nf][half * 2 + 0];
                float v1 = acc[mf][nf][half * 2 + 1];
                float* cp = C + (size_t)crow * N + col;
                if (combine) {
                    atomicAdd(cp, w * v0);
                    atomicAdd(cp + 1, w * v1);
                } else {
                    cp[0] = v0;
                    cp[1] = v1;
                }
            }
        }
    }
}

// ================= gated dual-B GEMM: C = gelu(A*B0) * (A*B1) =================
// Block tile 128 x 64(out) x 32. 8 warps (4xM, 2xN), warp tile 32x32 per B.
// Bs smem holds B0 in cols [0,64), B1 in cols [64,128).
__global__ void __launch_bounds__(256, 2)
bf16_gated_kernel(const float* __restrict__ A,
                  const float* __restrict__ B0g,
                  const float* __restrict__ B1g,
                  float* __restrict__ Cg,
                  int M, int Nout, int K,
                  const int* __restrict__ aIdxg,
                  const int* __restrict__ cntg,
                  size_t bZStr, size_t cZStr, int idxZStr)
{
    int z = blockIdx.z;
    const float* B0 = B0g + (size_t)z * bZStr;
    const float* B1 = B1g + (size_t)z * bZStr;
    float* C = Cg + (size_t)z * cZStr;
    const int* aIdx = aIdxg ? aIdxg + (size_t)z * idxZStr : nullptr;
    int Meff = cntg ? min(M, cntg[z]) : M;
    int bm = blockIdx.y * 128;
    int bnn = blockIdx.x * 64;
    if (bm >= Meff) return;

    __shared__ unsigned AsH[128 * BAST];
    __shared__ unsigned AsL[128 * BAST];
    __shared__ unsigned BsH[32 * BBST];
    __shared__ unsigned BsL[32 * BBST];

    int tid = threadIdx.x;
    int wid = tid >> 5;
    int lane = tid & 31;
    int gid = lane >> 2;
    int tgid = lane & 3;
    int wm = (wid & 3) * 32;
    int wn32 = (wid >> 2) * 32;

    int a_m = tid >> 3;
    int a_kq = tid & 7;

    unsigned aBaseH = (unsigned)__cvta_generic_to_shared(AsH);
    unsigned aBaseL = (unsigned)__cvta_generic_to_shared(AsL);
    unsigned bBaseH = (unsigned)__cvta_generic_to_shared(BsH);
    unsigned bBaseL = (unsigned)__cvta_generic_to_shared(BsL);
    int l15 = lane & 15;
    int lHi8 = (lane >> 4) << 3;

    float acc0[2][4][4], acc1[2][4][4];
    #pragma unroll
    for (int i = 0; i < 2; i++)
        #pragma unroll
        for (int j = 0; j < 4; j++)
            #pragma unroll
            for (int c = 0; c < 4; c++) { acc0[i][j][c] = 0.f; acc1[i][j][c] = 0.f; }

    for (int k0 = 0; k0 < K; k0 += 32) {
        #pragma unroll
        for (int p = 0; p < 4; p++) {
            int m = a_m + 32 * p;
            int gr = bm + m;
            float4 va = make_float4(0.f, 0.f, 0.f, 0.f);
            if (gr < Meff) {
                int ar = aIdx ? aIdx[gr] : gr;
                va = *reinterpret_cast<const float4*>(A + (size_t)ar * K + k0 + a_kq * 4);
            }
            int base = m * BAST + 2 * a_kq;
            unsigned h0, l0, h1, l1;
            split_pack(va.x, va.y, h0, l0);
            split_pack(va.z, va.w, h1, l1);
            AsH[base] = h0; AsH[base + 1] = h1;
            AsL[base] = l0; AsL[base + 1] = l1;
        }
        // B0/B1: 32 rows x (16+16) float4
        #pragma unroll
        for (int p = 0; p < 4; p++) {
            int lin = tid + p * 256;
            int kk = lin >> 5;
            int rest = lin & 31;
            int wb = rest >> 4;
            int f4 = rest & 15;
            const float* src = wb ? B1 : B0;
            float4 vb = *reinterpret_cast<const float4*>(src + (size_t)(k0 + kk) * Nout + bnn + f4 * 4);
            int base = kk * BBST + wb * 32 + f4 * 2;
            unsigned h0, l0, h1, l1;
            split_pack(vb.x, vb.y, h0, l0);
            split_pack(vb.z, vb.w, h1, l1);
            BsH[base] = h0; BsH[base + 1] = h1;
            BsL[base] = l0; BsL[base + 1] = l1;
        }
        __syncthreads();

        #pragma unroll
        for (int ks = 0; ks < 2; ks++) {
            int kk = ks * 16;
            unsigned ah[2][4], al[2][4];
            #pragma unroll
            for (int mf = 0; mf < 2; mf++) {
                int mrow = wm + mf * 16 + l15;
                unsigned off = (unsigned)(mrow * (BAST * 4) + (kk + lHi8) * 2);
                LDSM4(ah[mf][0], ah[mf][1], ah[mf][2], ah[mf][3], aBaseH + off);
                LDSM4(al[mf][0], al[mf][1], al[mf][2], al[mf][3], aBaseL + off);
            }
            int krow = kk + l15;
            // B0 then B1
            #pragma unroll
            for (int which = 0; which < 2; which++) {
                unsigned bfr[4][2];
                int colbase = which * 64 + wn32;
                #pragma unroll
                for (int nfp = 0; nfp < 2; nfp++) {
                    int ncol = colbase + nfp * 16 + lHi8;
                    unsigned off = (unsigned)(krow * (BBST * 4) + ncol * 2);
                    LDSM4T(bfr[2 * nfp][0], bfr[2 * nfp][1],
                           bfr[2 * nfp + 1][0], bfr[2 * nfp + 1][1], bBaseH + off);
                }
                #pragma unroll
                for (int mf = 0; mf < 2; mf++)
                    #pragma unroll
                    for (int nf = 0; nf < 4; nf++) {
                        float* a = which ? acc1[mf][nf] : acc0[mf][nf];
                        MMA_BF16(a[0], a[1], a[2], a[3],
                                 ah[mf][0], ah[mf][1], ah[mf][2], ah[mf][3],
                                 bfr[nf][0], bfr[nf][1]);
                        MMA_BF16(a[0], a[1], a[2], a[3],
                                 al[mf][0], al[mf][1], al[mf][2], al[mf][3],
                                 bfr[nf][0], bfr[nf][1]);
                    }
                #pragma unroll
                for (int nfp = 0; nfp < 2; nfp++) {
                    int ncol = colbase + nfp * 16 + lHi8;
                    unsigned off = (unsigned)(krow * (BBST * 4) + ncol * 2);
                    LDSM4T(bfr[2 * nfp][0], bfr[2 * nfp][1],
                           bfr[2 * nfp + 1][0], bfr[2 * nfp + 1][1], bBaseL + off);
                }
                #pragma unroll
                for (int mf = 0; mf < 2; mf++)
                    #pragma unroll
                    for (int nf = 0; nf < 4; nf++) {
                        float* a = which ? acc1[mf][nf] : acc0[mf][nf];
                        MMA_BF16(a[0], a[1], a[2], a[3],
                                 ah[mf][0], ah[mf][1], ah[mf][2], ah[mf][3],
                                 bfr[nf][0], bfr[nf][1]);
                    }
            }
        }
        __syncthreads();
    }

    #pragma unroll
    for (int mf = 0; mf < 2; mf++) {
        #pragma unroll
        for (int half = 0; half < 2; half++) {
            int row = bm + wm + mf * 16 + gid + half * 8;
            if (row >= Meff) continue;
            #pragma unroll
            for (int nf = 0; nf < 4; nf++) {
                int col = bnn + wn32 + nf * 8 + 2 * tgid;
                float g0v = gelu_tanh(acc0[mf][nf][half * 2 + 0]) * acc1[mf][nf][half * 2 + 0];
                float g1v = gelu_tanh(acc0[mf][nf][half * 2 + 1]) * acc1[mf][nf][half * 2 + 1];
                float* cp = C + (size_t)row * Nout + col;
                cp[0] = g0v;
                cp[1] = g1v;
            }
        }
    }
}

// ---------------- router ----------------
__global__ void router_kernel(const float* __restrict__ gin,
                              const float* __restrict__ wg,
                              float* __restrict__ combine,
                              int* __restrict__ cnt,
                              int* __restrict__ idx,
                              float* __restrict__ psum)
{
    int tok = blockIdx.x;
    int tid = threadIdx.x;
    float s[EE] = {};
    const float* g = gin + (size_t)tok * DD;
    for (int d = tid; d < DD; d += 256) {
        float gv = g[d];
        const float* w = wg + d * EE;
        #pragma unroll
        for (int e = 0; e < EE; e++) s[e] += gv * w[e];
    }
    __shared__ float sh[256][EE];
    #pragma unroll
    for (int e = 0; e < EE; e++) sh[tid][e] = s[e];
    __syncthreads();
    for (int str = 128; str > 0; str >>= 1) {
        if (tid < str) {
            #pragma unroll
            for (int e = 0; e < EE; e++) sh[tid][e] += sh[tid + str][e];
        }
        __syncthreads();
    }
    if (tid == 0) {
        float lg[EE], pe[EE];
        float mx = -FLT_MAX;
        #pragma unroll
        for (int e = 0; e < EE; e++) { lg[e] = sh[0][e]; mx = fmaxf(mx, lg[e]); }
        float sum = 0.f;
        #pragma unroll
        for (int e = 0; e < EE; e++) { pe[e] = expf(lg[e] - mx); sum += pe[e]; }
        float inv = 1.0f / sum;
        #pragma unroll
        for (int e = 0; e < EE; e++) { pe[e] *= inv; atomicAdd(&psum[e], pe[e]); }
        int i0 = 0;
        #pragma unroll
        for (int e = 1; e < EE; e++) if (pe[e] > pe[i0]) i0 = e;
        int i1 = (i0 == 0) ? 1 : 0;
        #pragma unroll
        for (int e = 0; e < EE; e++) if (e != i0 && e != i1 && pe[e] > pe[i1]) i1 = e;
        float tot = pe[i0] + pe[i1];
        float w0 = pe[i0] / tot, w1 = pe[i1] / tot;
        float* crow = combine + (size_t)tok * EE;
        #pragma unroll
        for (int e = 0; e < EE; e++) crow[e] = 0.f;
        crow[i0] = w0; crow[i1] = w1;
        int p0 = atomicAdd(&cnt[i0], 1); idx[i0 * TT + p0] = tok;
        int p1 = atomicAdd(&cnt[i1], 1); idx[i1 * TT + p1] = tok;
    }
}

// ---------------- load-balance loss ----------------
__global__ void lb_kernel(const int* __restrict__ cnt, const float* __restrict__ psum,
                          float* __restrict__ out)
{
    float lb = 0.f;
    #pragma unroll
    for (int e = 0; e < EE; e++)
        lb += ((float)cnt[e] / (float)TT) * (psum[e] / (float)TT);
    out[0] = lb * ((float)(EE * EE) / (float)EE);
}

// ==================== host launcher ====================
extern "C" void kernel_launch(void* const* d_in, const int* in_sizes, int n_in,
                              void* d_out, int out_size)
{
    const int*   positions       = (const int*)  d_in[0];
    const float* x               = (const float*)d_in[1];
    const float* pre_attn_scale  = (const float*)d_in[2];
    const float* wq              = (const float*)d_in[3];
    const float* wk              = (const float*)d_in[4];
    const float* wv              = (const float*)d_in[5];
    const float* wo              = (const float*)d_in[6];
    const float* q_norm_scale    = (const float*)d_in[7];
    const float* k_norm_scale    = (const float*)d_in[8];
    const float* v_norm_scale    = (const float*)d_in[9];
    const float* post_attn_scale = (const float*)d_in[10];
    const float* pre_ffw_scale   = (const float*)d_in[11];
    const float* shared_wi0      = (const float*)d_in[12];
    const float* shared_wi1      = (const float*)d_in[13];
    const float* shared_wo       = (const float*)d_in[14];
    const float* post_ff1_scale  = (const float*)d_in[15];
    const float* pre_ff2_scale   = (const float*)d_in[16];
    const float* router_scale    = (const float*)d_in[17];
    const float* w_gate          = (const float*)d_in[18];
    const float* ewi0            = (const float*)d_in[19];
    const float* ewi1            = (const float*)d_in[20];
    const float* ewo             = (const float*)d_in[21];
    const float* post_ff2_scale  = (const float*)d_in[22];
    const float* layer_scalar    = (const float*)d_in[23];
    float* out = (float*)d_out;

    static int smemConfigured = 0;
    if (!smemConfigured) {
        cudaFuncSetAttribute(fattn_kernel,
                             cudaFuncAttributeMaxDynamicSharedMemorySize,
                             ATT_SMEM_BYTES);
        smemConfigured = 1;
    }

    float* sc = nullptr;
    int*   isc = nullptr;
    cudaGetSymbolAddress((void**)&sc, g_scratch);
    cudaGetSymbolAddress((void**)&isc, g_iscratch);

    float* lnx   = sc + OFF_LNX;
    float* qb    = sc + OFF_Q;
    float* kb    = sc + OFF_K;
    float* vb    = sc + OFF_V;
    float* ob    = sc + OFF_O;
    float* attnb = sc + OFF_ATTN;
    float* hb    = sc + OFF_H;
    float* ffin  = sc + OFF_FFIN;
    float* g0    = sc + OFF_G0;
    float* egAll = sc + OFF_EGALL;
    float* shb   = sc + OFF_SH;
    float* rin   = sc + OFF_RIN;
    float* gin   = sc + OFF_GIN;
    float* routb = sc + OFF_ROUT;
    float* comb  = sc + OFF_COMB;
    float* psum  = sc + OFF_PSUM;
    int* idx = isc;
    int* cnt = isc + EE * TT;

    auto gemm_bf = [&](const float* A, const float* Bm, float* C, int M, int N, int K) {
        dim3 grid(N / 128, (M + 127) / 128, 1);
        bf16_gemm_kernel<<<grid, 256>>>(A, Bm, C, M, N, K,
                                        nullptr, nullptr, nullptr, nullptr, 0, 0, 0);
    };

    // 1) pre-attn norm
    rms_kernel<<<TT, 256>>>(x, pre_attn_scale, 1.f, nullptr, nullptr, nullptr, lnx);

    // 2) QKV projections
    gemm_bf(lnx, wq, qb, TT, HQ * HD, DD);
    gemm_bf(lnx, wk, kb, TT, HKV * HD, DD);
    gemm_bf(lnx, wv, vb, TT, HKV * HD, DD);

    // 3) per-head norms + rope
    head_norm_rope_kernel<<<TT * HQ, HD>>>(qb, q_norm_scale, positions, HQ, 1);
    head_norm_rope_kernel<<<TT * HKV, HD>>>(kb, k_norm_scale, positions, HKV, 1);
    head_norm_rope_kernel<<<TT * HKV, HD>>>(vb, v_norm_scale, positions, HKV, 0);

    // 4) attention (tensor-core flash)
    {
        dim3 grid(SS / ATQ, HQ, BB);
        fattn_kernel<<<grid, 256, ATT_SMEM_BYTES>>>(qb, kb, vb, ob);
    }

    // 5) output projection + post-attn norm + residual
    gemm_bf(ob, wo, attnb, TT, DD, HQ * HD);
    rms_kernel<<<TT, 256>>>(attnb, post_attn_scale, 1.f, x, nullptr, nullptr, hb);

    // 6) shared FFN: fused gated GEMM, then down-proj
    rms_kernel<<<TT, 256>>>(hb, pre_ffw_scale, 1.f, nullptr, nullptr, nullptr, ffin);
    {
        dim3 grid(FS / 64, TT / 128, 1);
        bf16_gated_kernel<<<grid, 256>>>(ffin, shared_wi0, shared_wi1, g0,
                                         TT, FS, DD, nullptr, nullptr, 0, 0, 0);
    }
    gemm_bf(g0, shared_wo, shb, TT, DD, FS);
    rms_kernel<<<TT, 256>>>(shb, post_ff1_scale, 1.f, nullptr, nullptr, nullptr, shb);

    // 7) router inputs
    rms_kernel<<<TT, 256>>>(hb, pre_ff2_scale, 1.f, nullptr, nullptr, nullptr, rin);
    rms_kernel<<<TT, 256>>>(hb, router_scale, 0.02209708691207961f /*D^-0.5*/,
                            nullptr, nullptr, nullptr, gin);

    // 8) router + batched MoE (all experts in z-dim)
    cudaMemsetAsync(cnt, 0, EE * sizeof(int));
    cudaMemsetAsync(psum, 0, EE * sizeof(float));
    cudaMemsetAsync(routb, 0, SZ_TD * sizeof(float));
    router_kernel<<<TT, 256>>>(gin, w_gate, comb, cnt, idx, psum);

    {
        // gated wi for all experts: A gathered from rin, out rows = expert-local positions
        dim3 grid(FE / 64, TT / 128, EE);
        bf16_gated_kernel<<<grid, 256>>>(rin, ewi0, ewi1, egAll,
                                         TT, FE, DD, idx, cnt,
                                         (size_t)DD * FE, (size_t)TT * FE, TT);
    }
    {
        // wo for all experts: scatter to routb with combine weights (atomic)
        dim3 grid(DD / 128, TT / 128, EE);
        bf16_gemm_kernel<<<grid, 256>>>(egAll, ewo, routb, TT, DD, FE,
                                        nullptr, idx, cnt, comb,
                                        (size_t)TT * FE, (size_t)FE * DD, TT);
    }

    // 9) final combine
    rms_kernel<<<TT, 256>>>(routb, post_ff2_scale, 1.f, shb, hb, layer_scalar, out);

    // 10) lb loss
    if (out_size > TT * DD) {
        lb_kernel<<<1, 1>>>(cnt, psum, out + (size_t)TT * DD);
    }
}